// round 1
// baseline (speedup 1.0000x reference)
#include <cuda_runtime.h>
#include <cuda_bf16.h>
#include <math.h>

// Problem dims
#define BATCH 2048
#define TT    128
#define VV    256
#define CC    32
#define HH    128
#define EE    256
#define GG    384   // 3*H
#define OO    256
#define NLN   3
#define BNK   32

// GRU kernel tiling
#define BM    32     // batch rows per CTA
#define NTH   192    // 48 gate-groups(x8) * 4 row-groups(x8)
#define RNPAD 132    // padded row length for r/n staging

// Scratch (static device globals - no runtime allocation)
__device__ float g_xtab[2 * VV * GG];   // (char_embed @ w_ih^T + b_ih) per dir
__device__ float g_feat[BATCH * EE];    // [h_f | h_b]

// ---------------------------------------------------------------------------
// Fast sigmoid/tanh on the FMA pipe only (no MUFU).
// exp(-|x|) via exp2: round-to-int magic + degree-5 poly on [-0.5,0.5];
// 1/(1+e) with denominator in [1,2]: linear minimax seed + 2 Newton steps.
// abs error ~1.5e-5.
// ---------------------------------------------------------------------------
__device__ __forceinline__ float fast_sigmoid(float x) {
    float ax = fminf(fabsf(x), 30.0f);
    float t  = ax * -1.4426950408889634f;        // -|x| * log2(e), in [-43.3, 0]
    float z  = t + 12582912.0f;                  // round-to-nearest-int trick
    int   ii = __float_as_int(z) - 0x4B400000;   // integer part
    float f  = t - (z - 12582912.0f);            // frac in [-0.5, 0.5]
    float p  = 1.3333558146428443e-3f;
    p = fmaf(p, f, 9.618129107628477e-3f);
    p = fmaf(p, f, 5.550410866482158e-2f);
    p = fmaf(p, f, 2.402265069591007e-1f);
    p = fmaf(p, f, 6.931471805599453e-1f);
    p = fmaf(p, f, 1.0f);
    float e = __int_as_float((127 + ii) << 23) * p;   // exp(-|x|) in (0,1]
    float d = 1.0f + e;                               // in [1,2]
    float y = fmaf(d, -0.4705882352941176f, 1.4117647058823530f); // ~1/d seed
    y = y * fmaf(-d, y, 2.0f);                        // Newton 1
    y = y * fmaf(-d, y, 2.0f);                        // Newton 2 -> ~1.2e-5 rel
    return x >= 0.0f ? y : e * y;                     // sigmoid(x)
}

__device__ __forceinline__ float fast_tanh(float x) {
    return fmaf(2.0f, fast_sigmoid(2.0f * x), -1.0f);
}

// ---------------------------------------------------------------------------
// Kernel A: xproj table  table[d][v][g] = dot(char_embed[v], w_ih_d[g]) + b_ih_d[g]
// ---------------------------------------------------------------------------
__global__ void xtab_kernel(const float* __restrict__ ce,
                            const float* __restrict__ wih_f, const float* __restrict__ bih_f,
                            const float* __restrict__ wih_b, const float* __restrict__ bih_b) {
    const int v = blockIdx.x;
    const int d = blockIdx.y;
    const int g = threadIdx.x;
    __shared__ float cs[CC];
    if (threadIdx.x < CC) cs[threadIdx.x] = ce[v * CC + threadIdx.x];
    __syncthreads();
    const float* wih = d ? wih_b : wih_f;
    const float* bih = d ? bih_b : bih_f;
    float s = bih[g];
    #pragma unroll
    for (int c = 0; c < CC; c++) s = fmaf(cs[c], wih[g * CC + c], s);
    g_xtab[(d * VV + v) * GG + g] = s;
}

// ---------------------------------------------------------------------------
// Kernel B: fused bidirectional GRU. grid (64, 2), 192 threads.
// SMEM: w_hh transposed [128][384] fp32 (196.6KB) + h [128][32] + r/n staging.
// Thread (rg,gg) owns an 8-row x 8-gate register tile; per step:
//   acc = b_hh + h @ w_hh^T (register-tiled GEMM, conflict-free LDS),
//   gather xp from L2 table, gate math in 3 phases (r -> n -> h-update).
// ---------------------------------------------------------------------------
__global__ __launch_bounds__(NTH, 1) void gru_kernel(
    const int* __restrict__ tokens,
    const float* __restrict__ whh_f, const float* __restrict__ whh_b,
    const float* __restrict__ bhh_f, const float* __restrict__ bhh_b) {
    extern __shared__ float sm[];
    float* w_s  = sm;                    // [128][384]
    float* h_s  = w_s + HH * GG;         // [128][32]   h[k][m]
    float* rn_s = h_s + HH * BM;         // [32][132]   r then n, in-place
    float* bh_s = rn_s + BM * RNPAD;     // [384]

    const int dir    = blockIdx.y;
    const int b_base = blockIdx.x * BM;
    const int tid    = threadIdx.x;
    const int rg     = tid & 3;          // row group
    const int gg     = tid >> 2;         // gate group 0..47
    const int m0     = rg * 8;
    const int g0     = gg * 8;

    const float* whh = dir ? whh_b : whh_f;
    const float* bhh = dir ? bhh_b : bhh_f;
    const float* xt  = g_xtab + dir * VV * GG;

    // Load w_hh transposed into SMEM (one-time)
    for (int idx = tid; idx < GG * HH; idx += NTH) {
        int g = idx >> 7, k = idx & (HH - 1);
        w_s[k * GG + g] = whh[idx];
    }
    for (int i = tid; i < GG; i += NTH) bh_s[i] = bhh[i];
    for (int i = tid; i < HH * BM; i += NTH) h_s[i] = 0.0f;
    __syncthreads();

    float bh[8];
    #pragma unroll
    for (int c = 0; c < 8; c++) bh[c] = bh_s[g0 + c];

    for (int t = 0; t < TT; t++) {
        const int tcol = dir ? (TT - 1 - t) : t;
        int tok[8];
        #pragma unroll
        for (int r = 0; r < 8; r++)
            tok[r] = tokens[(b_base + m0 + r) * TT + tcol];

        float acc[8][8];
        #pragma unroll
        for (int r = 0; r < 8; r++)
            #pragma unroll
            for (int c = 0; c < 8; c++) acc[r][c] = bh[c];

        // ---- register-tiled GEMM: acc += h @ w_hh^T ----
        #pragma unroll 4
        for (int k = 0; k < HH; k++) {
            float4 w0 = *(const float4*)(w_s + k * GG + g0);
            float4 w1 = *(const float4*)(w_s + k * GG + g0 + 4);
            float4 h0 = *(const float4*)(h_s + k * BM + m0);
            float4 h1 = *(const float4*)(h_s + k * BM + m0 + 4);
            float wv[8] = {w0.x, w0.y, w0.z, w0.w, w1.x, w1.y, w1.z, w1.w};
            float hv[8] = {h0.x, h0.y, h0.z, h0.w, h1.x, h1.y, h1.z, h1.w};
            #pragma unroll
            for (int r = 0; r < 8; r++)
                #pragma unroll
                for (int c = 0; c < 8; c++)
                    acc[r][c] = fmaf(hv[r], wv[c], acc[r][c]);
        }

        // ---- gather xp (L2-resident table) ----
        float xp[8][8];
        #pragma unroll
        for (int r = 0; r < 8; r++) {
            const float4* xr = (const float4*)(xt + tok[r] * GG + g0);
            float4 v0 = xr[0], v1 = xr[1];
            xp[r][0] = v0.x; xp[r][1] = v0.y; xp[r][2] = v0.z; xp[r][3] = v0.w;
            xp[r][4] = v1.x; xp[r][5] = v1.y; xp[r][6] = v1.z; xp[r][7] = v1.w;
        }

        __syncthreads();   // GEMM reads of h_s complete; rn_s reuse safe

        if (gg < 16) {                     // r gates -> stage to SMEM
            #pragma unroll
            for (int r = 0; r < 8; r++) {
                float4 o0, o1;
                o0.x = fast_sigmoid(xp[r][0] + acc[r][0]);
                o0.y = fast_sigmoid(xp[r][1] + acc[r][1]);
                o0.z = fast_sigmoid(xp[r][2] + acc[r][2]);
                o0.w = fast_sigmoid(xp[r][3] + acc[r][3]);
                o1.x = fast_sigmoid(xp[r][4] + acc[r][4]);
                o1.y = fast_sigmoid(xp[r][5] + acc[r][5]);
                o1.z = fast_sigmoid(xp[r][6] + acc[r][6]);
                o1.w = fast_sigmoid(xp[r][7] + acc[r][7]);
                *(float4*)(rn_s + (m0 + r) * RNPAD + g0)     = o0;
                *(float4*)(rn_s + (m0 + r) * RNPAD + g0 + 4) = o1;
            }
        } else if (gg < 32) {              // z gates -> keep in regs (reuse acc)
            #pragma unroll
            for (int r = 0; r < 8; r++)
                #pragma unroll
                for (int c = 0; c < 8; c++)
                    acc[r][c] = fast_sigmoid(xp[r][c] + acc[r][c]);
        }
        __syncthreads();

        if (gg >= 32) {                    // n gates: n = tanh(xn + r*hn)
            const int j0 = g0 - 2 * HH;
            #pragma unroll
            for (int r = 0; r < 8; r++) {
                float4 r0 = *(const float4*)(rn_s + (m0 + r) * RNPAD + j0);
                float4 r1 = *(const float4*)(rn_s + (m0 + r) * RNPAD + j0 + 4);
                float rv[8] = {r0.x, r0.y, r0.z, r0.w, r1.x, r1.y, r1.z, r1.w};
                float4 o0, o1;
                o0.x = fast_tanh(fmaf(rv[0], acc[r][0], xp[r][0]));
                o0.y = fast_tanh(fmaf(rv[1], acc[r][1], xp[r][1]));
                o0.z = fast_tanh(fmaf(rv[2], acc[r][2], xp[r][2]));
                o0.w = fast_tanh(fmaf(rv[3], acc[r][3], xp[r][3]));
                o1.x = fast_tanh(fmaf(rv[4], acc[r][4], xp[r][4]));
                o1.y = fast_tanh(fmaf(rv[5], acc[r][5], xp[r][5]));
                o1.z = fast_tanh(fmaf(rv[6], acc[r][6], xp[r][6]));
                o1.w = fast_tanh(fmaf(rv[7], acc[r][7], xp[r][7]));
                *(float4*)(rn_s + (m0 + r) * RNPAD + j0)     = o0;  // in-place n
                *(float4*)(rn_s + (m0 + r) * RNPAD + j0 + 4) = o1;
            }
        }
        __syncthreads();

        if (gg >= 16 && gg < 32) {         // h' = n + z*(h - n)
            const int j0 = g0 - HH;
            #pragma unroll
            for (int r = 0; r < 8; r++) {
                float4 n0 = *(const float4*)(rn_s + (m0 + r) * RNPAD + j0);
                float4 n1 = *(const float4*)(rn_s + (m0 + r) * RNPAD + j0 + 4);
                float nv[8] = {n0.x, n0.y, n0.z, n0.w, n1.x, n1.y, n1.z, n1.w};
                #pragma unroll
                for (int c = 0; c < 8; c++) {
                    int hidx = (j0 + c) * BM + (m0 + r);
                    float hold = h_s[hidx];
                    h_s[hidx] = fmaf(acc[r][c], hold - nv[c], nv[c]);
                }
            }
        }
        __syncthreads();
    }

    // write final hidden state to feat
    for (int idx = tid; idx < HH * BM; idx += NTH) {
        int k = idx >> 5, m = idx & (BM - 1);
        g_feat[(b_base + m) * EE + dir * HH + k] = h_s[k * BM + m];
    }
}

// ---------------------------------------------------------------------------
// Kernel C: adapter (lang-routed bottleneck) + LayerNorm + projection.
// 16 batch rows per CTA so proj_w (256KB) is streamed 128x, not 2048x.
// ---------------------------------------------------------------------------
#define CB 16
__global__ __launch_bounds__(256) void head_kernel(
    const int* __restrict__ lang_ids,
    const float* __restrict__ down_w, const float* __restrict__ down_b,
    const float* __restrict__ up_w,   const float* __restrict__ up_b,
    const float* __restrict__ ln_g,   const float* __restrict__ ln_b,
    const float* __restrict__ proj_w, const float* __restrict__ proj_b,
    float* __restrict__ out) {
    __shared__ float f_s[CB][EE + 4];
    __shared__ float y_s[CB][EE + 4];
    __shared__ float hid_s[BNK];
    __shared__ float red1[8], red2[8];
    __shared__ float mu_sh, rstd_sh;

    const int tid  = threadIdx.x;
    const int b0   = blockIdx.x * CB;
    const int w    = tid >> 5;
    const int lane = tid & 31;

    for (int idx = tid; idx < CB * EE; idx += 256) {
        int r = idx >> 8, e = idx & 255;
        f_s[r][e] = g_feat[(b0 + r) * EE + e];
    }
    __syncthreads();

    for (int r = 0; r < CB; r++) {
        const int b = b0 + r;
        const int l = lang_ids[b];
        // down-proj + exact GELU: warp w computes units w*4..w*4+3
        #pragma unroll
        for (int q = 0; q < 4; q++) {
            const int d = w * 4 + q;
            const float* dw = down_w + (l * BNK + d) * EE;
            float s = 0.0f;
            #pragma unroll
            for (int i = 0; i < 8; i++)
                s = fmaf(f_s[r][lane + 32 * i], dw[lane + 32 * i], s);
            #pragma unroll
            for (int o = 16; o; o >>= 1) s += __shfl_down_sync(0xffffffffu, s, o);
            if (lane == 0) {
                float v = s + down_b[l * BNK + d];
                hid_s[d] = 0.5f * v * (1.0f + erff(v * 0.7071067811865476f));
            }
        }
        __syncthreads();
        // up-proj + residual
        const int e = tid;
        float a = up_b[l * EE + e];
        const float* uw = up_w + (l * EE + e) * BNK;
        #pragma unroll
        for (int d = 0; d < BNK; d++) a = fmaf(hid_s[d], uw[d], a);
        float x = f_s[r][e] + a;
        // LayerNorm (population variance)
        float s1 = x, s2 = x * x;
        #pragma unroll
        for (int o = 16; o; o >>= 1) {
            s1 += __shfl_down_sync(0xffffffffu, s1, o);
            s2 += __shfl_down_sync(0xffffffffu, s2, o);
        }
        if (lane == 0) { red1[w] = s1; red2[w] = s2; }
        __syncthreads();
        if (tid == 0) {
            float t1 = 0.0f, t2 = 0.0f;
            #pragma unroll
            for (int i = 0; i < 8; i++) { t1 += red1[i]; t2 += red2[i]; }
            float mu  = t1 * (1.0f / EE);
            float var = t2 * (1.0f / EE) - mu * mu;
            mu_sh = mu;
            rstd_sh = rsqrtf(var + 1e-5f);
        }
        __syncthreads();
        y_s[r][e] = (x - mu_sh) * rstd_sh * ln_g[l * EE + e] + ln_b[l * EE + e];
        __syncthreads();
    }

    // projection: thread owns output column `tid` for all 16 rows
    float accv[CB];
    #pragma unroll
    for (int r = 0; r < CB; r++) accv[r] = proj_b[tid];
    const float* pw = proj_w + tid * EE;
    for (int e = 0; e < EE; e += 4) {
        float4 wv = *(const float4*)(pw + e);
        #pragma unroll
        for (int r = 0; r < CB; r++) {
            float4 yv = *(const float4*)(&y_s[r][e]);
            accv[r] = fmaf(wv.x, yv.x, accv[r]);
            accv[r] = fmaf(wv.y, yv.y, accv[r]);
            accv[r] = fmaf(wv.z, yv.z, accv[r]);
            accv[r] = fmaf(wv.w, yv.w, accv[r]);
        }
    }
    #pragma unroll
    for (int r = 0; r < CB; r++) out[(b0 + r) * OO + tid] = accv[r];
}

// ---------------------------------------------------------------------------
extern "C" void kernel_launch(void* const* d_in, const int* in_sizes, int n_in,
                              void* d_out, int out_size) {
    const int*   tokens = (const int*)d_in[0];
    const int*   lang   = (const int*)d_in[1];
    const float* ce     = (const float*)d_in[2];
    const float* wih_f  = (const float*)d_in[3];
    const float* whh_f  = (const float*)d_in[4];
    const float* bih_f  = (const float*)d_in[5];
    const float* bhh_f  = (const float*)d_in[6];
    const float* wih_b  = (const float*)d_in[7];
    const float* whh_b  = (const float*)d_in[8];
    const float* bih_b  = (const float*)d_in[9];
    const float* bhh_b  = (const float*)d_in[10];
    const float* down_w = (const float*)d_in[11];
    const float* down_b = (const float*)d_in[12];
    const float* up_w   = (const float*)d_in[13];
    const float* up_b   = (const float*)d_in[14];
    const float* ln_g   = (const float*)d_in[15];
    const float* ln_b   = (const float*)d_in[16];
    const float* proj_w = (const float*)d_in[17];
    const float* proj_b = (const float*)d_in[18];
    float* out = (float*)d_out;

    const size_t smemB = (size_t)(HH * GG + HH * BM + BM * RNPAD + GG) * sizeof(float);
    cudaFuncSetAttribute(gru_kernel, cudaFuncAttributeMaxDynamicSharedMemorySize, (int)smemB);

    xtab_kernel<<<dim3(VV, 2), GG>>>(ce, wih_f, bih_f, wih_b, bih_b);
    gru_kernel<<<dim3(BATCH / BM, 2), NTH, smemB>>>(tokens, whh_f, whh_b, bhh_f, bhh_b);
    head_kernel<<<BATCH / CB, 256>>>(lang, down_w, down_b, up_w, up_b,
                                     ln_g, ln_b, proj_w, proj_b, out);
}

// round 2
// speedup vs baseline: 2.7995x; 2.7995x over previous
#include <cuda_runtime.h>
#include <cuda_fp16.h>
#include <cuda_bf16.h>
#include <math.h>
#include <stdint.h>

// Problem dims
#define BATCH 2048
#define TT    128
#define VV    256
#define CC    32
#define HH    128
#define EE    256
#define GG    384   // 3*H
#define OO    256
#define BNK   32

// GRU tiling
#define BM    32      // batch rows per CTA
#define NTH   256     // 8 warps
// SMEM byte offsets
#define SW0   0                   // w split hi: [384][128] half, swizzled
#define SW1   98304               // w split lo
#define SH0   196608              // h split hi: [32][128] half, swizzled
#define SH1   204800              // h split lo
#define SMEM_TOTAL 212992

// Scratch (static device globals)
__device__ __align__(16) __half g_wsplit[2 * 2 * GG * HH]; // [dir][split][p][k]
__device__ float g_xtab[2 * VV * GG];   // permuted (x @ w_ih^T + b_ih) per dir
__device__ float g_feat[BATCH * EE];

// ---------------------------------------------------------------------------
// MUFU-based sigmoid/tanh: ex2.approx (err ~2^-22) + rcp.approx + 1 Newton.
// ---------------------------------------------------------------------------
__device__ __forceinline__ float sigm(float x) {
    float t = fminf(x * 1.4426950408889634f, 80.0f);
    float e; asm("ex2.approx.f32 %0, %1;" : "=f"(e) : "f"(t));
    float d = 1.0f + e;
    float y; asm("rcp.approx.f32 %0, %1;" : "=f"(y) : "f"(d));
    y = y * fmaf(-d, y, 2.0f);           // Newton
    return e * y;
}
__device__ __forceinline__ float tanh_(float x) {
    return fmaf(2.0f, sigm(2.0f * x), -1.0f);
}

// ---------------------------------------------------------------------------
// MMA / ldmatrix wrappers
// ---------------------------------------------------------------------------
__device__ __forceinline__ void ldsm4(uint32_t& r0, uint32_t& r1, uint32_t& r2,
                                      uint32_t& r3, uint32_t addr) {
    asm volatile("ldmatrix.sync.aligned.m8n8.x4.shared.b16 {%0,%1,%2,%3}, [%4];"
                 : "=r"(r0), "=r"(r1), "=r"(r2), "=r"(r3) : "r"(addr));
}
__device__ __forceinline__ void mma16816(float* d, uint32_t a0, uint32_t a1,
                                         uint32_t a2, uint32_t a3,
                                         uint32_t b0, uint32_t b1) {
    asm volatile(
        "mma.sync.aligned.m16n8k16.row.col.f32.f16.f16.f32 "
        "{%0,%1,%2,%3}, {%4,%5,%6,%7}, {%8,%9}, {%0,%1,%2,%3};"
        : "+f"(d[0]), "+f"(d[1]), "+f"(d[2]), "+f"(d[3])
        : "r"(a0), "r"(a1), "r"(a2), "r"(a3), "r"(b0), "r"(b1));
}

// gate-dim permutation: orig g = t*128 + j  ->  p = 48*(j>>4) + 16*t + (j&15)
__device__ __forceinline__ int permute_g(int g) {
    int t = g >> 7, j = g & 127;
    return 48 * (j >> 4) + 16 * t + (j & 15);
}

// ---------------------------------------------------------------------------
// Prep A: xtab (permuted)  xtab[d][v][p(g)] = dot(ce[v], w_ih[g]) + b_ih[g]
// ---------------------------------------------------------------------------
__global__ void xtab_kernel(const float* __restrict__ ce,
                            const float* __restrict__ wih_f, const float* __restrict__ bih_f,
                            const float* __restrict__ wih_b, const float* __restrict__ bih_b) {
    const int v = blockIdx.x, d = blockIdx.y, g = threadIdx.x;
    __shared__ float cs[CC];
    if (threadIdx.x < CC) cs[threadIdx.x] = ce[v * CC + threadIdx.x];
    __syncthreads();
    const float* wih = d ? wih_b : wih_f;
    const float* bih = d ? bih_b : bih_f;
    float s = bih[g];
    #pragma unroll
    for (int c = 0; c < CC; c++) s = fmaf(cs[c], wih[g * CC + c], s);
    g_xtab[(d * VV + v) * GG + permute_g(g)] = s;
}

// ---------------------------------------------------------------------------
// Prep B: w_hh fp16 2-way split, permuted rows.
// ---------------------------------------------------------------------------
__global__ void wsplit_kernel(const float* __restrict__ whh_f,
                              const float* __restrict__ whh_b) {
    const int d = blockIdx.x, g = threadIdx.x;
    const float* w = d ? whh_b : whh_f;
    const int p = permute_g(g);
    __half* w0 = g_wsplit + (d * 2 + 0) * (GG * HH);
    __half* w1 = g_wsplit + (d * 2 + 1) * (GG * HH);
    for (int k = 0; k < HH; k++) {
        float v = w[g * HH + k];
        __half h0 = __float2half_rn(v);
        __half h1 = __float2half_rn(v - __half2float(h0));
        w0[p * HH + k] = h0;
        w1[p * HH + k] = h1;
    }
}

// ---------------------------------------------------------------------------
// GRU via warp-level mma (fp16 split, fp32 accum). grid (64,2) x 256 thr.
// ---------------------------------------------------------------------------
__global__ __launch_bounds__(NTH, 1) void gru_mma_kernel(
    const int* __restrict__ tokens,
    const float* __restrict__ bhh_f, const float* __restrict__ bhh_b) {
    extern __shared__ __align__(16) char smem[];
    const uint32_t sb = (uint32_t)__cvta_generic_to_shared(smem);

    const int dir  = blockIdx.y;
    const int b0r  = blockIdx.x * BM;
    const int tid  = threadIdx.x;
    const int w    = tid >> 5;
    const int lane = tid & 31;
    const int lr   = lane >> 2;     // row-in-tile 0..7
    const int lq   = lane & 3;      // col pair 0..3

    const float* bhh = dir ? bhh_b : bhh_f;
    const float* xt  = g_xtab + dir * VV * GG;

    // ---- load w splits to SMEM with 16B-chunk XOR swizzle ----
    {
        const uint4* gw0 = (const uint4*)(g_wsplit + (dir * 2 + 0) * (GG * HH));
        const uint4* gw1 = (const uint4*)(g_wsplit + (dir * 2 + 1) * (GG * HH));
        for (int idx = tid; idx < GG * 16; idx += NTH) {
            int n = idx >> 4, c = idx & 15;
            int off = n * 256 + ((c ^ (n & 7)) << 4);
            *(uint4*)(smem + SW0 + off) = gw0[idx];
            *(uint4*)(smem + SW1 + off) = gw1[idx];
        }
        // zero h0/h1
        for (int idx = tid; idx < 1024; idx += NTH)
            ((uint4*)(smem + SH0))[idx] = make_uint4(0, 0, 0, 0);
    }

    // ---- per-thread constants ----
    float bias[3][4];
    #pragma unroll
    for (int t = 0; t < 3; t++)
        #pragma unroll
        for (int qi = 0; qi < 4; qi++) {
            int q = 8 * (qi >> 1) + 2 * lq + (qi & 1);
            bias[t][qi] = bhh[128 * t + 16 * w + q];
        }

    // A ldmatrix addressing constants
    const int ar  = lane & 15;       // row within m16 tile
    const int ahi = lane >> 4;       // chunk half-select
    const int asw = ar & 7;
    // B ldmatrix addressing constants
    const int bj   = lane >> 3;      // chunk select 0..3
    const int bsw  = lane & 7;
    const int brow = (48 * w + (lane & 7)) * 256;

    // h' STS byte offsets (same for both splits)
    int stoff[4][2];
    #pragma unroll
    for (int ri = 0; ri < 4; ri++)
        #pragma unroll
        for (int qh = 0; qh < 2; qh++)
            stoff[ri][qh] = (lr + 8 * ri) * 256 + ((((2 * w + qh) ^ lr)) << 4) + 4 * lq;

    float hprev[4][4];
    #pragma unroll
    for (int ri = 0; ri < 4; ri++)
        #pragma unroll
        for (int qi = 0; qi < 4; qi++) hprev[ri][qi] = 0.0f;

    __syncthreads();

    for (int t = 0; t < TT; t++) {
        const int tcol = dir ? (TT - 1 - t) : t;

        // ---- tokens + xp gather (issued early; completes under mma) ----
        int tok[4];
        #pragma unroll
        for (int ri = 0; ri < 4; ri++)
            tok[ri] = tokens[(b0r + lr + 8 * ri) * TT + tcol];
        float2 xp[4][6];  // [row][2*t + qh]
        #pragma unroll
        for (int ri = 0; ri < 4; ri++) {
            const float2* xr = (const float2*)(xt + tok[ri] * GG + 48 * w);
            #pragma unroll
            for (int u = 0; u < 6; u++)
                xp[ri][u] = xr[(u >> 1) * 8 + (u & 1) * 4 + lq];
        }

        // ---- accumulators init with b_hh ----
        float acc[2][6][4];
        #pragma unroll
        for (int mt = 0; mt < 2; mt++)
            #pragma unroll
            for (int nt = 0; nt < 6; nt++)
                #pragma unroll
                for (int rg = 0; rg < 4; rg++)
                    acc[mt][nt][rg] = bias[nt >> 1][(nt & 1) * 2 + (rg & 1)];

        // ---- mma mainloop over K=128 in k32 chunks ----
        #pragma unroll
        for (int kc2 = 0; kc2 < 4; kc2++) {
            uint32_t a[2][2][8];   // [split][mt][kk*4 + r]
            #pragma unroll
            for (int s = 0; s < 2; s++)
                #pragma unroll
                for (int mt = 0; mt < 2; mt++) {
                    uint32_t base = sb + (s ? SH1 : SH0) + mt * 4096 + ar * 256;
                    ldsm4(a[s][mt][0], a[s][mt][1], a[s][mt][2], a[s][mt][3],
                          base + ((((4 * kc2 + 0 + ahi) ^ asw)) << 4));
                    ldsm4(a[s][mt][4], a[s][mt][5], a[s][mt][6], a[s][mt][7],
                          base + ((((4 * kc2 + 2 + ahi) ^ asw)) << 4));
                }
            #pragma unroll
            for (int nt = 0; nt < 6; nt++) {
                uint32_t chunk = (uint32_t)(((4 * kc2 + bj) ^ bsw) << 4);
                uint32_t bh[4], bl[4];
                ldsm4(bh[0], bh[1], bh[2], bh[3], sb + SW0 + brow + nt * 2048 + chunk);
                ldsm4(bl[0], bl[1], bl[2], bl[3], sb + SW1 + brow + nt * 2048 + chunk);
                #pragma unroll
                for (int mt = 0; mt < 2; mt++)
                    #pragma unroll
                    for (int kk = 0; kk < 2; kk++) {
                        mma16816(acc[mt][nt], a[0][mt][kk*4], a[0][mt][kk*4+1],
                                 a[0][mt][kk*4+2], a[0][mt][kk*4+3],
                                 bh[kk*2], bh[kk*2+1]);
                        mma16816(acc[mt][nt], a[0][mt][kk*4], a[0][mt][kk*4+1],
                                 a[0][mt][kk*4+2], a[0][mt][kk*4+3],
                                 bl[kk*2], bl[kk*2+1]);
                        mma16816(acc[mt][nt], a[1][mt][kk*4], a[1][mt][kk*4+1],
                                 a[1][mt][kk*4+2], a[1][mt][kk*4+3],
                                 bh[kk*2], bh[kk*2+1]);
                    }
            }
        }

        __syncthreads();   // all warps' h reads done -> safe to overwrite h

        // ---- thread-local gate math + h' split/store ----
        #pragma unroll
        for (int ri = 0; ri < 4; ri++) {
            const int mt = ri >> 1, rr = ri & 1;
            float hv[4];
            #pragma unroll
            for (int qi = 0; qi < 4; qi++) {
                const int qh = qi >> 1, c01 = qi & 1, rg = 2 * rr + c01;
                float xr_ = (c01 ? xp[ri][0 + qh].y : xp[ri][0 + qh].x) + acc[mt][0 + qh][rg];
                float xz_ = (c01 ? xp[ri][2 + qh].y : xp[ri][2 + qh].x) + acc[mt][2 + qh][rg];
                float xn_ = (c01 ? xp[ri][4 + qh].y : xp[ri][4 + qh].x);
                float nh  = acc[mt][4 + qh][rg];
                float r = sigm(xr_);
                float z = sigm(xz_);
                float n = tanh_(fmaf(r, nh, xn_));
                float h = fmaf(z, hprev[ri][qi] - n, n);
                hprev[ri][qi] = h;
                hv[qi] = h;
            }
            #pragma unroll
            for (int qh = 0; qh < 2; qh++) {
                __half a0 = __float2half_rn(hv[2 * qh]);
                __half a1 = __float2half_rn(hv[2 * qh + 1]);
                __half c0 = __float2half_rn(hv[2 * qh]     - __half2float(a0));
                __half c1 = __float2half_rn(hv[2 * qh + 1] - __half2float(a1));
                *(__half2*)(smem + SH0 + stoff[ri][qh]) = __halves2half2(a0, a1);
                *(__half2*)(smem + SH1 + stoff[ri][qh]) = __halves2half2(c0, c1);
            }
        }
        __syncthreads();   // h' visible before next step's ldmatrix
    }

    // ---- write final hidden to feat ----
    #pragma unroll
    for (int ri = 0; ri < 4; ri++)
        #pragma unroll
        for (int qi = 0; qi < 4; qi++) {
            int m = lr + 8 * ri;
            int j = 16 * w + 8 * (qi >> 1) + 2 * lq + (qi & 1);
            g_feat[(b0r + m) * EE + dir * HH + j] = hprev[ri][qi];
        }
}

// ---------------------------------------------------------------------------
// Head: adapter + LayerNorm + projection (unchanged from R1).
// ---------------------------------------------------------------------------
#define CB 16
__global__ __launch_bounds__(256) void head_kernel(
    const int* __restrict__ lang_ids,
    const float* __restrict__ down_w, const float* __restrict__ down_b,
    const float* __restrict__ up_w,   const float* __restrict__ up_b,
    const float* __restrict__ ln_g,   const float* __restrict__ ln_b,
    const float* __restrict__ proj_w, const float* __restrict__ proj_b,
    float* __restrict__ out) {
    __shared__ float f_s[CB][EE + 4];
    __shared__ float y_s[CB][EE + 4];
    __shared__ float hid_s[BNK];
    __shared__ float red1[8], red2[8];
    __shared__ float mu_sh, rstd_sh;

    const int tid  = threadIdx.x;
    const int b0   = blockIdx.x * CB;
    const int w    = tid >> 5;
    const int lane = tid & 31;

    for (int idx = tid; idx < CB * EE; idx += 256) {
        int r = idx >> 8, e = idx & 255;
        f_s[r][e] = g_feat[(b0 + r) * EE + e];
    }
    __syncthreads();

    for (int r = 0; r < CB; r++) {
        const int b = b0 + r;
        const int l = lang_ids[b];
        #pragma unroll
        for (int q = 0; q < 4; q++) {
            const int d = w * 4 + q;
            const float* dw = down_w + (l * BNK + d) * EE;
            float s = 0.0f;
            #pragma unroll
            for (int i = 0; i < 8; i++)
                s = fmaf(f_s[r][lane + 32 * i], dw[lane + 32 * i], s);
            #pragma unroll
            for (int o = 16; o; o >>= 1) s += __shfl_down_sync(0xffffffffu, s, o);
            if (lane == 0) {
                float v = s + down_b[l * BNK + d];
                hid_s[d] = 0.5f * v * (1.0f + erff(v * 0.7071067811865476f));
            }
        }
        __syncthreads();
        const int e = tid;
        float a = up_b[l * EE + e];
        const float* uw = up_w + (l * EE + e) * BNK;
        #pragma unroll
        for (int d = 0; d < BNK; d++) a = fmaf(hid_s[d], uw[d], a);
        float x = f_s[r][e] + a;
        float s1 = x, s2 = x * x;
        #pragma unroll
        for (int o = 16; o; o >>= 1) {
            s1 += __shfl_down_sync(0xffffffffu, s1, o);
            s2 += __shfl_down_sync(0xffffffffu, s2, o);
        }
        if (lane == 0) { red1[w] = s1; red2[w] = s2; }
        __syncthreads();
        if (tid == 0) {
            float t1 = 0.0f, t2 = 0.0f;
            #pragma unroll
            for (int i = 0; i < 8; i++) { t1 += red1[i]; t2 += red2[i]; }
            float mu  = t1 * (1.0f / EE);
            float var = t2 * (1.0f / EE) - mu * mu;
            mu_sh = mu;
            rstd_sh = rsqrtf(var + 1e-5f);
        }
        __syncthreads();
        y_s[r][e] = (x - mu_sh) * rstd_sh * ln_g[l * EE + e] + ln_b[l * EE + e];
        __syncthreads();
    }

    float accv[CB];
    #pragma unroll
    for (int r = 0; r < CB; r++) accv[r] = proj_b[tid];
    const float* pw = proj_w + tid * EE;
    for (int e = 0; e < EE; e += 4) {
        float4 wv = *(const float4*)(pw + e);
        #pragma unroll
        for (int r = 0; r < CB; r++) {
            float4 yv = *(const float4*)(&y_s[r][e]);
            accv[r] = fmaf(wv.x, yv.x, accv[r]);
            accv[r] = fmaf(wv.y, yv.y, accv[r]);
            accv[r] = fmaf(wv.z, yv.z, accv[r]);
            accv[r] = fmaf(wv.w, yv.w, accv[r]);
        }
    }
    #pragma unroll
    for (int r = 0; r < CB; r++) out[(b0 + r) * OO + tid] = accv[r];
}

// ---------------------------------------------------------------------------
extern "C" void kernel_launch(void* const* d_in, const int* in_sizes, int n_in,
                              void* d_out, int out_size) {
    const int*   tokens = (const int*)d_in[0];
    const int*   lang   = (const int*)d_in[1];
    const float* ce     = (const float*)d_in[2];
    const float* wih_f  = (const float*)d_in[3];
    const float* whh_f  = (const float*)d_in[4];
    const float* bih_f  = (const float*)d_in[5];
    const float* bhh_f  = (const float*)d_in[6];
    const float* wih_b  = (const float*)d_in[7];
    const float* whh_b  = (const float*)d_in[8];
    const float* bih_b  = (const float*)d_in[9];
    const float* bhh_b  = (const float*)d_in[10];
    const float* down_w = (const float*)d_in[11];
    const float* down_b = (const float*)d_in[12];
    const float* up_w   = (const float*)d_in[13];
    const float* up_b   = (const float*)d_in[14];
    const float* ln_g   = (const float*)d_in[15];
    const float* ln_b   = (const float*)d_in[16];
    const float* proj_w = (const float*)d_in[17];
    const float* proj_b = (const float*)d_in[18];
    float* out = (float*)d_out;

    cudaFuncSetAttribute(gru_mma_kernel,
                         cudaFuncAttributeMaxDynamicSharedMemorySize, SMEM_TOTAL);

    wsplit_kernel<<<2, GG>>>(whh_f, whh_b);
    xtab_kernel<<<dim3(VV, 2), GG>>>(ce, wih_f, bih_f, wih_b, bih_b);
    gru_mma_kernel<<<dim3(BATCH / BM, 2), NTH, SMEM_TOTAL>>>(tokens, bhh_f, bhh_b);
    head_kernel<<<BATCH / CB, 256>>>(lang, down_w, down_b, up_w, up_b,
                                     ln_g, ln_b, proj_w, proj_b, out);
}

// round 3
// speedup vs baseline: 2.8222x; 1.0081x over previous
#include <cuda_runtime.h>
#include <cuda_fp16.h>
#include <cuda_bf16.h>
#include <math.h>
#include <stdint.h>

// Problem dims
#define BATCH 2048
#define TT    128
#define VV    256
#define CC    32
#define HH    128
#define EE    256
#define GG    384   // 3*H
#define OO    256
#define NLN   3
#define BNK   32

// GRU tiling
#define BM    32      // batch rows per CTA (2 streams x 16)
#define NTH   256     // 8 warps
// SMEM byte offsets
#define SW0   0                   // w split hi: [384][128] half, swizzled
#define SW1   98304               // w split lo
#define SHBASE 196608             // 4 h buffers: [stream][split] 4KB each
#define SHOFF(s, sp) (SHBASE + ((s) * 2 + (sp)) * 4096)
#define SMEM_TOTAL 212992

// Scratch (static device globals)
__device__ __align__(16) __half g_wsplit[2 * 2 * GG * HH]; // [dir][split][p][k]
__device__ float g_xtab[2 * VV * GG];   // permuted (x @ w_ih^T + b_ih) per dir
__device__ float g_feat[BATCH * EE];
__device__ float g_upwT[NLN * BNK * EE]; // up_w transposed: [l][d][e]

// ---------------------------------------------------------------------------
// MUFU sigmoid/tanh: ex2.approx + rcp.approx + 1 Newton.
// ---------------------------------------------------------------------------
__device__ __forceinline__ float sigm(float x) {
    float t = fminf(x * 1.4426950408889634f, 80.0f);
    float e; asm("ex2.approx.f32 %0, %1;" : "=f"(e) : "f"(t));
    float d = 1.0f + e;
    float y; asm("rcp.approx.f32 %0, %1;" : "=f"(y) : "f"(d));
    y = y * fmaf(-d, y, 2.0f);
    return e * y;
}
__device__ __forceinline__ float tanh_(float x) {
    return fmaf(2.0f, sigm(2.0f * x), -1.0f);
}

// ---------------------------------------------------------------------------
// MMA / ldmatrix wrappers
// ---------------------------------------------------------------------------
__device__ __forceinline__ void ldsm4(uint32_t& r0, uint32_t& r1, uint32_t& r2,
                                      uint32_t& r3, uint32_t addr) {
    asm volatile("ldmatrix.sync.aligned.m8n8.x4.shared.b16 {%0,%1,%2,%3}, [%4];"
                 : "=r"(r0), "=r"(r1), "=r"(r2), "=r"(r3) : "r"(addr));
}
__device__ __forceinline__ void mma16816(float* d, const uint32_t* a,
                                         uint32_t b0, uint32_t b1) {
    asm volatile(
        "mma.sync.aligned.m16n8k16.row.col.f32.f16.f16.f32 "
        "{%0,%1,%2,%3}, {%4,%5,%6,%7}, {%8,%9}, {%0,%1,%2,%3};"
        : "+f"(d[0]), "+f"(d[1]), "+f"(d[2]), "+f"(d[3])
        : "r"(a[0]), "r"(a[1]), "r"(a[2]), "r"(a[3]), "r"(b0), "r"(b1));
}

// gate-dim permutation: orig g = t*128 + j  ->  p = 48*(j>>4) + 16*t + (j&15)
__device__ __forceinline__ int permute_g(int g) {
    int t = g >> 7, j = g & 127;
    return 48 * (j >> 4) + 16 * t + (j & 15);
}

// ---------------------------------------------------------------------------
// Prep A: xtab (permuted), w_ih staged in SMEM for coalesced reuse.
// grid (8, 2) x 384 threads; dynamic smem 54KB.
// ---------------------------------------------------------------------------
__global__ void xtab_kernel(const float* __restrict__ ce,
                            const float* __restrict__ wih_f, const float* __restrict__ bih_f,
                            const float* __restrict__ wih_b, const float* __restrict__ bih_b) {
    extern __shared__ float xsm[];
    float* ws = xsm;               // [384*32]
    float* bs = ws + GG * CC;      // [384]
    float* cs = bs + GG;           // [32*32]
    const int d = blockIdx.y, g = threadIdx.x;
    const float* wih = d ? wih_b : wih_f;
    const float* bih = d ? bih_b : bih_f;
    for (int i = g; i < GG * CC; i += GG) ws[i] = wih[i];
    bs[g] = bih[g];
    const int v0 = blockIdx.x * 32;
    for (int i = g; i < 32 * CC; i += GG) cs[i] = ce[v0 * CC + i];
    __syncthreads();
    const int p = permute_g(g);
    for (int vi = 0; vi < 32; vi++) {
        float s = bs[g];
        #pragma unroll
        for (int c = 0; c < CC; c++) s = fmaf(cs[vi * CC + c], ws[g * CC + c], s);
        g_xtab[(d * VV + v0 + vi) * GG + p] = s;
    }
}

// ---------------------------------------------------------------------------
// Prep B: w_hh fp16 2-way split, permuted rows.
// ---------------------------------------------------------------------------
__global__ void wsplit_kernel(const float* __restrict__ whh_f,
                              const float* __restrict__ whh_b) {
    const int d = blockIdx.x, g = threadIdx.x;
    const float* w = d ? whh_b : whh_f;
    const int p = permute_g(g);
    __half* w0 = g_wsplit + (d * 2 + 0) * (GG * HH);
    __half* w1 = g_wsplit + (d * 2 + 1) * (GG * HH);
    for (int k = 0; k < HH; k++) {
        float v = w[g * HH + k];
        __half h0 = __float2half_rn(v);
        __half h1 = __float2half_rn(v - __half2float(h0));
        w0[p * HH + k] = h0;
        w1[p * HH + k] = h1;
    }
}

// ---------------------------------------------------------------------------
// Prep C: transpose up_w [l][e][d] -> [l][d][e] for coalesced head reads.
// ---------------------------------------------------------------------------
__global__ void upwT_kernel(const float* __restrict__ up_w) {
    for (int i = blockIdx.x * 256 + threadIdx.x; i < NLN * EE * BNK;
         i += gridDim.x * 256) {
        int l = i / (EE * BNK), rem = i % (EE * BNK);
        int e = rem / BNK, dd = rem % BNK;
        g_upwT[(l * BNK + dd) * EE + e] = up_w[i];
    }
}

// ---------------------------------------------------------------------------
// GRU: two interleaved 16-row streams so gate MUFU work and LDSM latency
// hide under the other stream's HMMA. grid (64,2) x 256 threads.
// ---------------------------------------------------------------------------
__global__ __launch_bounds__(NTH, 1) void gru_mma_kernel(
    const int* __restrict__ tokens,
    const float* __restrict__ bhh_f, const float* __restrict__ bhh_b) {
    extern __shared__ __align__(16) char smem[];
    const uint32_t sb = (uint32_t)__cvta_generic_to_shared(smem);

    const int dir  = blockIdx.y;
    const int b0r  = blockIdx.x * BM;
    const int tid  = threadIdx.x;
    const int w    = tid >> 5;
    const int lane = tid & 31;
    const int lr   = lane >> 2;
    const int lq   = lane & 3;

    const float* bhh = dir ? bhh_b : bhh_f;
    const float* xt  = g_xtab + dir * VV * GG;

    // ---- load w splits (swizzled) + zero h buffers ----
    {
        const uint4* gw0 = (const uint4*)(g_wsplit + (dir * 2 + 0) * (GG * HH));
        const uint4* gw1 = (const uint4*)(g_wsplit + (dir * 2 + 1) * (GG * HH));
        for (int idx = tid; idx < GG * 16; idx += NTH) {
            int n = idx >> 4, c = idx & 15;
            int off = n * 256 + ((c ^ (n & 7)) << 4);
            *(uint4*)(smem + SW0 + off) = gw0[idx];
            *(uint4*)(smem + SW1 + off) = gw1[idx];
        }
        for (int idx = tid; idx < 1024; idx += NTH)
            ((uint4*)(smem + SHBASE))[idx] = make_uint4(0, 0, 0, 0);
    }

    float bias[3][4];
    #pragma unroll
    for (int t = 0; t < 3; t++)
        #pragma unroll
        for (int qi = 0; qi < 4; qi++)
            bias[t][qi] = bhh[128 * t + 16 * w + 8 * (qi >> 1) + 2 * lq + (qi & 1)];

    const int ar  = lane & 15;
    const int ahi = lane >> 4;
    const int asw = ar & 7;
    const int bj  = lane >> 3;
    const int bsw = lane & 7;
    const int brow = (48 * w + (lane & 7)) * 256;

    int stoff[2][2];
    #pragma unroll
    for (int ri = 0; ri < 2; ri++)
        #pragma unroll
        for (int qh = 0; qh < 2; qh++)
            stoff[ri][qh] = (lr + 8 * ri) * 256 + (((2 * w + qh) ^ lr) << 4) + 4 * lq;

    float hprev[2][2][4];
    float acc[2][6][4];
    #pragma unroll
    for (int s = 0; s < 2; s++) {
        #pragma unroll
        for (int ri = 0; ri < 2; ri++)
            #pragma unroll
            for (int qi = 0; qi < 4; qi++) hprev[s][ri][qi] = 0.0f;
        #pragma unroll
        for (int nt = 0; nt < 6; nt++)
            #pragma unroll
            for (int rg = 0; rg < 4; rg++)
                acc[s][nt][rg] = bias[nt >> 1][(nt & 1) * 2 + (rg & 1)];
    }

    __syncthreads();

    for (int t = 0; t < TT; t++) {
        const int tcol = dir ? (TT - 1 - t) : t;

        // xp for both streams (s0 consumed in phase 0, s1 in phase 1)
        float2 xp[2][2][6];
        #pragma unroll
        for (int s = 0; s < 2; s++)
            #pragma unroll
            for (int ri = 0; ri < 2; ri++) {
                int tok = tokens[(b0r + 16 * s + lr + 8 * ri) * TT + tcol];
                const float2* xr = (const float2*)(xt + tok * GG + 48 * w);
                #pragma unroll
                for (int u = 0; u < 6; u++)
                    xp[s][ri][u] = xr[(u >> 1) * 8 + (u & 1) * 4 + lq];
            }

        #pragma unroll
        for (int ph = 0; ph < 2; ph++) {
            const int sm = 1 - ph;   // mma stream
            const int sg = ph;       // gate stream

            // reset mma-stream accumulators to bias
            #pragma unroll
            for (int nt = 0; nt < 6; nt++)
                #pragma unroll
                for (int rg = 0; rg < 4; rg++)
                    acc[sm][nt][rg] = bias[nt >> 1][(nt & 1) * 2 + (rg & 1)];

            const bool do_mma = ph ? (t < TT - 1) : (t > 0);
            if (do_mma) {
                const uint32_t ab0 = sb + SHOFF(sm, 0) + ar * 256;
                const uint32_t ab1 = sb + SHOFF(sm, 1) + ar * 256;
                #pragma unroll
                for (int kc2 = 0; kc2 < 4; kc2++) {
                    uint32_t a0[8], a1[8];
                    uint32_t clo = (uint32_t)(((4 * kc2 + 0 + ahi) ^ asw) << 4);
                    uint32_t chi = (uint32_t)(((4 * kc2 + 2 + ahi) ^ asw) << 4);
                    ldsm4(a0[0], a0[1], a0[2], a0[3], ab0 + clo);
                    ldsm4(a0[4], a0[5], a0[6], a0[7], ab0 + chi);
                    ldsm4(a1[0], a1[1], a1[2], a1[3], ab1 + clo);
                    ldsm4(a1[4], a1[5], a1[6], a1[7], ab1 + chi);

                    const uint32_t chunk = (uint32_t)(((4 * kc2 + bj) ^ bsw) << 4);
                    uint32_t bh[2][4], bl[2][4];
                    ldsm4(bh[0][0], bh[0][1], bh[0][2], bh[0][3],
                          sb + SW0 + brow + chunk);
                    ldsm4(bl[0][0], bl[0][1], bl[0][2], bl[0][3],
                          sb + SW1 + brow + chunk);
                    #pragma unroll
                    for (int nt = 0; nt < 6; nt++) {
                        const int cur = nt & 1, nxt = cur ^ 1;
                        if (nt < 5) {
                            ldsm4(bh[nxt][0], bh[nxt][1], bh[nxt][2], bh[nxt][3],
                                  sb + SW0 + brow + (nt + 1) * 2048 + chunk);
                            ldsm4(bl[nxt][0], bl[nxt][1], bl[nxt][2], bl[nxt][3],
                                  sb + SW1 + brow + (nt + 1) * 2048 + chunk);
                        }
                        #pragma unroll
                        for (int kk = 0; kk < 2; kk++) {
                            mma16816(acc[sm][nt], a0 + kk * 4, bh[cur][kk*2], bh[cur][kk*2+1]);
                            mma16816(acc[sm][nt], a0 + kk * 4, bl[cur][kk*2], bl[cur][kk*2+1]);
                            mma16816(acc[sm][nt], a1 + kk * 4, bh[cur][kk*2], bh[cur][kk*2+1]);
                        }
                    }
                }
            }

            // gates for stream sg (independent of the mma above -> overlaps)
            #pragma unroll
            for (int ri = 0; ri < 2; ri++) {
                float hv[4];
                #pragma unroll
                for (int qi = 0; qi < 4; qi++) {
                    const int qh = qi >> 1, c01 = qi & 1, rg = 2 * ri + c01;
                    float xr_ = (c01 ? xp[sg][ri][0 + qh].y : xp[sg][ri][0 + qh].x)
                                + acc[sg][0 + qh][rg];
                    float xz_ = (c01 ? xp[sg][ri][2 + qh].y : xp[sg][ri][2 + qh].x)
                                + acc[sg][2 + qh][rg];
                    float xn_ = (c01 ? xp[sg][ri][4 + qh].y : xp[sg][ri][4 + qh].x);
                    float nh  = acc[sg][4 + qh][rg];
                    float r = sigm(xr_);
                    float z = sigm(xz_);
                    float n = tanh_(fmaf(r, nh, xn_));
                    float h = fmaf(z, hprev[sg][ri][qi] - n, n);
                    hprev[sg][ri][qi] = h;
                    hv[qi] = h;
                }
                #pragma unroll
                for (int qh = 0; qh < 2; qh++) {
                    __half A0 = __float2half_rn(hv[2 * qh]);
                    __half A1 = __float2half_rn(hv[2 * qh + 1]);
                    __half C0 = __float2half_rn(hv[2 * qh]     - __half2float(A0));
                    __half C1 = __float2half_rn(hv[2 * qh + 1] - __half2float(A1));
                    *(__half2*)(smem + SHOFF(sg, 0) + stoff[ri][qh]) = __halves2half2(A0, A1);
                    *(__half2*)(smem + SHOFF(sg, 1) + stoff[ri][qh]) = __halves2half2(C0, C1);
                }
            }
            __syncthreads();
        }
    }

    // final hidden -> feat
    #pragma unroll
    for (int s = 0; s < 2; s++)
        #pragma unroll
        for (int ri = 0; ri < 2; ri++)
            #pragma unroll
            for (int qi = 0; qi < 4; qi++) {
                int m = 16 * s + lr + 8 * ri;
                int j = 16 * w + 8 * (qi >> 1) + 2 * lq + (qi & 1);
                g_feat[(b0r + m) * EE + dir * HH + j] = hprev[s][ri][qi];
            }
}

// ---------------------------------------------------------------------------
// Head: warp-per-row adapter + LN (no CTA barriers), then tiled projection.
// grid 128 x 256 threads, 16 rows per CTA.
// ---------------------------------------------------------------------------
#define HB 16
__global__ __launch_bounds__(256) void head_kernel(
    const int* __restrict__ lang_ids,
    const float* __restrict__ down_w, const float* __restrict__ down_b,
    const float* __restrict__ up_b,
    const float* __restrict__ ln_g,   const float* __restrict__ ln_b,
    const float* __restrict__ proj_w, const float* __restrict__ proj_b,
    float* __restrict__ out) {
    __shared__ float y_s[HB][EE];
    const int tid = threadIdx.x, w = tid >> 5, lane = tid & 31;
    const int b0 = blockIdx.x * HB;

    #pragma unroll
    for (int rr = 0; rr < 2; rr++) {
        const int r = w + 8 * rr;
        const int b = b0 + r;
        const int l = lang_ids[b];
        const float4 fx0 = *(const float4*)(g_feat + b * EE + lane * 8);
        const float4 fx1 = *(const float4*)(g_feat + b * EE + lane * 8 + 4);

        // down-proj: each of 32 units via full-warp dot + xor-butterfly
        const float* dwb = down_w + l * BNK * EE;
        float hid = 0.0f;
        #pragma unroll 4
        for (int d = 0; d < BNK; d++) {
            float4 w0 = *(const float4*)(dwb + d * EE + lane * 8);
            float4 w1 = *(const float4*)(dwb + d * EE + lane * 8 + 4);
            float s = fx0.x * w0.x;
            s = fmaf(fx0.y, w0.y, s); s = fmaf(fx0.z, w0.z, s);
            s = fmaf(fx0.w, w0.w, s); s = fmaf(fx1.x, w1.x, s);
            s = fmaf(fx1.y, w1.y, s); s = fmaf(fx1.z, w1.z, s);
            s = fmaf(fx1.w, w1.w, s);
            #pragma unroll
            for (int o = 16; o; o >>= 1) s += __shfl_xor_sync(0xffffffffu, s, o);
            if (lane == d) hid = s;
        }
        hid += down_b[l * BNK + lane];
        hid = 0.5f * hid * (1.0f + erff(hid * 0.7071067811865476f));

        // up-proj (transposed weights, coalesced) + residual
        float4 a0 = *(const float4*)(up_b + l * EE + lane * 8);
        float4 a1 = *(const float4*)(up_b + l * EE + lane * 8 + 4);
        const float* uwb = g_upwT + l * BNK * EE;
        #pragma unroll 4
        for (int d = 0; d < BNK; d++) {
            float hd = __shfl_sync(0xffffffffu, hid, d);
            float4 u0 = *(const float4*)(uwb + d * EE + lane * 8);
            float4 u1 = *(const float4*)(uwb + d * EE + lane * 8 + 4);
            a0.x = fmaf(hd, u0.x, a0.x); a0.y = fmaf(hd, u0.y, a0.y);
            a0.z = fmaf(hd, u0.z, a0.z); a0.w = fmaf(hd, u0.w, a0.w);
            a1.x = fmaf(hd, u1.x, a1.x); a1.y = fmaf(hd, u1.y, a1.y);
            a1.z = fmaf(hd, u1.z, a1.z); a1.w = fmaf(hd, u1.w, a1.w);
        }
        float x[8] = {fx0.x + a0.x, fx0.y + a0.y, fx0.z + a0.z, fx0.w + a0.w,
                      fx1.x + a1.x, fx1.y + a1.y, fx1.z + a1.z, fx1.w + a1.w};
        float s1 = 0.0f, s2 = 0.0f;
        #pragma unroll
        for (int j = 0; j < 8; j++) { s1 += x[j]; s2 = fmaf(x[j], x[j], s2); }
        #pragma unroll
        for (int o = 16; o; o >>= 1) {
            s1 += __shfl_xor_sync(0xffffffffu, s1, o);
            s2 += __shfl_xor_sync(0xffffffffu, s2, o);
        }
        const float mu = s1 * (1.0f / EE);
        const float rstd = rsqrtf(s2 * (1.0f / EE) - mu * mu + 1e-5f);
        const float4 g0 = *(const float4*)(ln_g + l * EE + lane * 8);
        const float4 g1 = *(const float4*)(ln_g + l * EE + lane * 8 + 4);
        const float4 bb0 = *(const float4*)(ln_b + l * EE + lane * 8);
        const float4 bb1 = *(const float4*)(ln_b + l * EE + lane * 8 + 4);
        float4 y0, y1;
        y0.x = (x[0]-mu)*rstd*g0.x + bb0.x;  y0.y = (x[1]-mu)*rstd*g0.y + bb0.y;
        y0.z = (x[2]-mu)*rstd*g0.z + bb0.z;  y0.w = (x[3]-mu)*rstd*g0.w + bb0.w;
        y1.x = (x[4]-mu)*rstd*g1.x + bb1.x;  y1.y = (x[5]-mu)*rstd*g1.y + bb1.y;
        y1.z = (x[6]-mu)*rstd*g1.z + bb1.z;  y1.w = (x[7]-mu)*rstd*g1.w + bb1.w;
        *(float4*)(&y_s[r][lane * 8])     = y0;
        *(float4*)(&y_s[r][lane * 8 + 4]) = y1;
    }
    __syncthreads();

    // projection: thread owns output column `tid` for all 16 rows
    float accv[HB];
    #pragma unroll
    for (int r = 0; r < HB; r++) accv[r] = proj_b[tid];
    const float* pw = proj_w + tid * EE;
    for (int e = 0; e < EE; e += 4) {
        float4 wv = *(const float4*)(pw + e);
        #pragma unroll
        for (int r = 0; r < HB; r++) {
            float4 yv = *(const float4*)(&y_s[r][e]);
            accv[r] = fmaf(wv.x, yv.x, accv[r]);
            accv[r] = fmaf(wv.y, yv.y, accv[r]);
            accv[r] = fmaf(wv.z, yv.z, accv[r]);
            accv[r] = fmaf(wv.w, yv.w, accv[r]);
        }
    }
    #pragma unroll
    for (int r = 0; r < HB; r++) out[(b0 + r) * OO + tid] = accv[r];
}

// ---------------------------------------------------------------------------
extern "C" void kernel_launch(void* const* d_in, const int* in_sizes, int n_in,
                              void* d_out, int out_size) {
    const int*   tokens = (const int*)d_in[0];
    const int*   lang   = (const int*)d_in[1];
    const float* ce     = (const float*)d_in[2];
    const float* wih_f  = (const float*)d_in[3];
    const float* whh_f  = (const float*)d_in[4];
    const float* bih_f  = (const float*)d_in[5];
    const float* bhh_f  = (const float*)d_in[6];
    const float* wih_b  = (const float*)d_in[7];
    const float* whh_b  = (const float*)d_in[8];
    const float* bih_b  = (const float*)d_in[9];
    const float* bhh_b  = (const float*)d_in[10];
    const float* down_w = (const float*)d_in[11];
    const float* down_b = (const float*)d_in[12];
    const float* up_w   = (const float*)d_in[13];
    const float* up_b   = (const float*)d_in[14];
    const float* ln_g   = (const float*)d_in[15];
    const float* ln_b   = (const float*)d_in[16];
    const float* proj_w = (const float*)d_in[17];
    const float* proj_b = (const float*)d_in[18];
    float* out = (float*)d_out;

    cudaFuncSetAttribute(gru_mma_kernel,
                         cudaFuncAttributeMaxDynamicSharedMemorySize, SMEM_TOTAL);
    const size_t xsmem = (size_t)(GG * CC + GG + 32 * CC) * sizeof(float);
    cudaFuncSetAttribute(xtab_kernel,
                         cudaFuncAttributeMaxDynamicSharedMemorySize, (int)xsmem);

    wsplit_kernel<<<2, GG>>>(whh_f, whh_b);
    xtab_kernel<<<dim3(8, 2), GG, xsmem>>>(ce, wih_f, bih_f, wih_b, bih_b);
    upwT_kernel<<<96, 256>>>(up_w);
    gru_mma_kernel<<<dim3(BATCH / BM, 2), NTH, SMEM_TOTAL>>>(tokens, bhh_f, bhh_b);
    head_kernel<<<BATCH / HB, 256>>>(lang, down_w, down_b, up_b,
                                     ln_g, ln_b, proj_w, proj_b, out);
}

// round 4
// speedup vs baseline: 3.3723x; 1.1949x over previous
#include <cuda_runtime.h>
#include <cuda_fp16.h>
#include <cuda_bf16.h>
#include <math.h>
#include <stdint.h>

// Problem dims
#define BATCH 2048
#define TT    128
#define VV    256
#define CC    32
#define HH    128
#define EE    256
#define GG    384   // 3*H
#define OO    256
#define NLN   3
#define BNK   32

// GRU tiling
#define BM    32      // batch rows per CTA (2 streams x 16)
#define NTH   512     // 16 warps, 24 gate-cols each
// SMEM byte offsets
#define SW0   0                   // w split hi: [384][128] half, swizzled
#define SW1   98304               // w split lo
#define SHBASE 196608             // 4 h buffers: [stream][split] 4KB each
#define SHOFF(s, sp) (SHBASE + ((s) * 2 + (sp)) * 4096)
#define SMEM_TOTAL 212992

// Scratch (static device globals)
__device__ __align__(16) __half g_wsplit[2 * 2 * GG * HH]; // [dir][split][p][k]
__device__ float g_xtab[2 * VV * GG];   // permuted (x @ w_ih^T + b_ih) per dir
__device__ float g_feat[BATCH * EE];
__device__ float g_upwT[NLN * BNK * EE]; // up_w transposed: [l][d][e]

// ---------------------------------------------------------------------------
// MUFU sigmoid/tanh: ex2.approx + rcp.approx + 1 Newton.
// ---------------------------------------------------------------------------
__device__ __forceinline__ float sigm(float x) {
    float t = fminf(x * 1.4426950408889634f, 80.0f);
    float e; asm("ex2.approx.f32 %0, %1;" : "=f"(e) : "f"(t));
    float d = 1.0f + e;
    float y; asm("rcp.approx.f32 %0, %1;" : "=f"(y) : "f"(d));
    y = y * fmaf(-d, y, 2.0f);
    return e * y;
}
__device__ __forceinline__ float tanh_(float x) {
    return fmaf(2.0f, sigm(2.0f * x), -1.0f);
}

// ---------------------------------------------------------------------------
// MMA / ldmatrix wrappers
// ---------------------------------------------------------------------------
__device__ __forceinline__ void ldsm4(uint32_t& r0, uint32_t& r1, uint32_t& r2,
                                      uint32_t& r3, uint32_t addr) {
    asm volatile("ldmatrix.sync.aligned.m8n8.x4.shared.b16 {%0,%1,%2,%3}, [%4];"
                 : "=r"(r0), "=r"(r1), "=r"(r2), "=r"(r3) : "r"(addr));
}
__device__ __forceinline__ void mma16816(float* d, const uint32_t* a,
                                         uint32_t b0, uint32_t b1) {
    asm volatile(
        "mma.sync.aligned.m16n8k16.row.col.f32.f16.f16.f32 "
        "{%0,%1,%2,%3}, {%4,%5,%6,%7}, {%8,%9}, {%0,%1,%2,%3};"
        : "+f"(d[0]), "+f"(d[1]), "+f"(d[2]), "+f"(d[3])
        : "r"(a[0]), "r"(a[1]), "r"(a[2]), "r"(a[3]), "r"(b0), "r"(b1));
}

// gate-dim permutation for 16 warps (24 cols each):
// orig g = t*128 + j  ->  p = 24*(j>>3) + 8*t + (j&7)
__device__ __forceinline__ int permute_g(int g) {
    int t = g >> 7, j = g & 127;
    return 24 * (j >> 3) + 8 * t + (j & 7);
}

// ---------------------------------------------------------------------------
// Prep A: xtab (permuted), w_ih staged in SMEM. grid (8, 2) x 384.
// ---------------------------------------------------------------------------
__global__ void xtab_kernel(const float* __restrict__ ce,
                            const float* __restrict__ wih_f, const float* __restrict__ bih_f,
                            const float* __restrict__ wih_b, const float* __restrict__ bih_b) {
    extern __shared__ float xsm[];
    float* ws = xsm;               // [384*32]
    float* bs = ws + GG * CC;      // [384]
    float* cs = bs + GG;           // [32*32]
    const int d = blockIdx.y, g = threadIdx.x;
    const float* wih = d ? wih_b : wih_f;
    const float* bih = d ? bih_b : bih_f;
    for (int i = g; i < GG * CC; i += GG) ws[i] = wih[i];
    bs[g] = bih[g];
    const int v0 = blockIdx.x * 32;
    for (int i = g; i < 32 * CC; i += GG) cs[i] = ce[v0 * CC + i];
    __syncthreads();
    const int p = permute_g(g);
    for (int vi = 0; vi < 32; vi++) {
        float s = bs[g];
        #pragma unroll
        for (int c = 0; c < CC; c++) s = fmaf(cs[vi * CC + c], ws[g * CC + c], s);
        g_xtab[(d * VV + v0 + vi) * GG + p] = s;
    }
}

// ---------------------------------------------------------------------------
// Prep B: w_hh fp16 2-way split, permuted. grid (2, 384) x 128 threads.
// ---------------------------------------------------------------------------
__global__ void wsplit_kernel(const float* __restrict__ whh_f,
                              const float* __restrict__ whh_b) {
    const int d = blockIdx.x, g = blockIdx.y, k = threadIdx.x;
    const float* w = d ? whh_b : whh_f;
    float v = w[g * HH + k];
    __half h0 = __float2half_rn(v);
    __half h1 = __float2half_rn(v - __half2float(h0));
    const int p = permute_g(g);
    __half* base = g_wsplit + d * 2 * (GG * HH);
    base[p * HH + k] = h0;
    base[GG * HH + p * HH + k] = h1;
}

// ---------------------------------------------------------------------------
// Prep C: transpose up_w [l][e][d] -> [l][d][e].
// ---------------------------------------------------------------------------
__global__ void upwT_kernel(const float* __restrict__ up_w) {
    for (int i = blockIdx.x * 256 + threadIdx.x; i < NLN * EE * BNK;
         i += gridDim.x * 256) {
        int l = i / (EE * BNK), rem = i % (EE * BNK);
        int e = rem / BNK, dd = rem % BNK;
        g_upwT[(l * BNK + dd) * EE + e] = up_w[i];
    }
}

// ---------------------------------------------------------------------------
// GRU via mma, 16 warps, gate cells interleaved into the mma k-loop.
// grid (64, 2) x 512 threads.
// ---------------------------------------------------------------------------
__global__ __launch_bounds__(NTH, 1) void gru_mma_kernel(
    const int* __restrict__ tokens,
    const float* __restrict__ bhh_f, const float* __restrict__ bhh_b) {
    extern __shared__ __align__(16) char smem[];
    const uint32_t sb = (uint32_t)__cvta_generic_to_shared(smem);

    const int dir  = blockIdx.y;
    const int b0r  = blockIdx.x * BM;
    const int tid  = threadIdx.x;
    const int w    = tid >> 5;      // 0..15
    const int lane = tid & 31;
    const int lr   = lane >> 2;     // 0..7
    const int lq   = lane & 3;      // 0..3

    const float* bhh = dir ? bhh_b : bhh_f;
    const float* xt  = g_xtab + dir * VV * GG;

    // ---- load w splits (swizzled) + zero h buffers ----
    {
        const uint4* gw0 = (const uint4*)(g_wsplit + (dir * 2 + 0) * (GG * HH));
        const uint4* gw1 = (const uint4*)(g_wsplit + (dir * 2 + 1) * (GG * HH));
        for (int idx = tid; idx < GG * 16; idx += NTH) {
            int n = idx >> 4, c = idx & 15;
            int off = n * 256 + ((c ^ (n & 7)) << 4);
            *(uint4*)(smem + SW0 + off) = gw0[idx];
            *(uint4*)(smem + SW1 + off) = gw1[idx];
        }
        for (int idx = tid; idx < 1024; idx += NTH)
            ((uint4*)(smem + SHBASE))[idx] = make_uint4(0, 0, 0, 0);
    }

    // biases for this thread's 2 gate columns (j = 8w + 2lq + {0,1})
    float bias[3][2];
    #pragma unroll
    for (int t = 0; t < 3; t++)
        #pragma unroll
        for (int c = 0; c < 2; c++)
            bias[t][c] = bhh[t * 128 + 8 * w + 2 * lq + c];

    // ldmatrix addressing constants
    const int ar  = lane & 15;
    const int ahi = lane >> 4;
    const int asw = ar & 7;
    const int bj  = lane >> 3;
    const int bsw = lane & 7;
    const int brow = (24 * w + (lane & 7)) * 256;

    // h' store offsets (chunk index = w since unit j = 8w + ..)
    int stoff[2];
    #pragma unroll
    for (int ri = 0; ri < 2; ri++)
        stoff[ri] = (lr + 8 * ri) * 256 + ((w ^ lr) << 4) + 4 * lq;

    float hprev[2][2][2];
    float acc[2][3][4];
    #pragma unroll
    for (int s = 0; s < 2; s++) {
        #pragma unroll
        for (int ri = 0; ri < 2; ri++)
            #pragma unroll
            for (int c = 0; c < 2; c++) hprev[s][ri][c] = 0.0f;
        #pragma unroll
        for (int nt = 0; nt < 3; nt++)
            #pragma unroll
            for (int rg = 0; rg < 4; rg++)
                acc[s][nt][rg] = bias[nt][rg & 1];
    }

    __syncthreads();

    #pragma unroll 1
    for (int t = 0; t < TT; t++) {
        const int tcol = dir ? (TT - 1 - t) : t;

        // xp gather for both streams (L2 table; consumed in gate cells)
        float2 xp[2][2][3];
        #pragma unroll
        for (int s = 0; s < 2; s++)
            #pragma unroll
            for (int ri = 0; ri < 2; ri++) {
                int tok = tokens[(b0r + 16 * s + lr + 8 * ri) * TT + tcol];
                const float2* xr = (const float2*)(xt + tok * GG + 24 * w);
                #pragma unroll
                for (int u = 0; u < 3; u++)
                    xp[s][ri][u] = xr[4 * u + lq];
            }

        #pragma unroll
        for (int ph = 0; ph < 2; ph++) {
            const int sm_ = 1 - ph;   // mma stream
            const int sg  = ph;       // gate stream

            // reset mma-stream accumulators to bias
            #pragma unroll
            for (int nt = 0; nt < 3; nt++)
                #pragma unroll
                for (int rg = 0; rg < 4; rg++)
                    acc[sm_][nt][rg] = bias[nt][rg & 1];

            const bool do_mma = ph ? (t < TT - 1) : (t > 0);
            const uint32_t ab0 = sb + SHOFF(sm_, 0) + ar * 256;
            const uint32_t ab1 = sb + SHOFF(sm_, 1) + ar * 256;

            #pragma unroll
            for (int kc2 = 0; kc2 < 4; kc2++) {
                uint32_t a0[8], a1[8];
                if (do_mma) {
                    uint32_t clo = (uint32_t)(((4 * kc2 + ahi) ^ asw) << 4);
                    uint32_t chi = (uint32_t)(((4 * kc2 + 2 + ahi) ^ asw) << 4);
                    ldsm4(a0[0], a0[1], a0[2], a0[3], ab0 + clo);
                    ldsm4(a0[4], a0[5], a0[6], a0[7], ab0 + chi);
                    ldsm4(a1[0], a1[1], a1[2], a1[3], ab1 + clo);
                    ldsm4(a1[4], a1[5], a1[6], a1[7], ab1 + chi);
                }

                // one gate cell of the gate stream, interleaved with mma
                {
                    const int ri = kc2 >> 1, c01 = kc2 & 1, rg = 2 * ri + c01;
                    float xr_ = (c01 ? xp[sg][ri][0].y : xp[sg][ri][0].x)
                                + acc[sg][0][rg];
                    float xz_ = (c01 ? xp[sg][ri][1].y : xp[sg][ri][1].x)
                                + acc[sg][1][rg];
                    float xn_ = (c01 ? xp[sg][ri][2].y : xp[sg][ri][2].x);
                    float nh  = acc[sg][2][rg];
                    float r = sigm(xr_);
                    float z = sigm(xz_);
                    float n = tanh_(fmaf(r, nh, xn_));
                    float h = fmaf(z, hprev[sg][ri][c01] - n, n);
                    hprev[sg][ri][c01] = h;
                    __half hh = __float2half_rn(h);
                    __half hl = __float2half_rn(h - __half2float(hh));
                    const int so = stoff[ri] + 2 * c01;
                    *(__half*)(smem + SHOFF(sg, 0) + so) = hh;
                    *(__half*)(smem + SHOFF(sg, 1) + so) = hl;
                }

                if (do_mma) {
                    const uint32_t chunk = (uint32_t)(((4 * kc2 + bj) ^ bsw) << 4);
                    #pragma unroll
                    for (int nt = 0; nt < 3; nt++) {
                        uint32_t bh[4], bl[4];
                        ldsm4(bh[0], bh[1], bh[2], bh[3],
                              sb + SW0 + brow + nt * 2048 + chunk);
                        ldsm4(bl[0], bl[1], bl[2], bl[3],
                              sb + SW1 + brow + nt * 2048 + chunk);
                        #pragma unroll
                        for (int kk = 0; kk < 2; kk++) {
                            mma16816(acc[sm_][nt], a0 + kk * 4, bh[kk*2], bh[kk*2+1]);
                            mma16816(acc[sm_][nt], a0 + kk * 4, bl[kk*2], bl[kk*2+1]);
                            mma16816(acc[sm_][nt], a1 + kk * 4, bh[kk*2], bh[kk*2+1]);
                        }
                    }
                }
            }
            __syncthreads();
        }
    }

    // final hidden -> feat
    #pragma unroll
    for (int s = 0; s < 2; s++)
        #pragma unroll
        for (int ri = 0; ri < 2; ri++)
            #pragma unroll
            for (int c = 0; c < 2; c++) {
                int m = 16 * s + lr + 8 * ri;
                int j = 8 * w + 2 * lq + c;
                g_feat[(b0r + m) * EE + dir * HH + j] = hprev[s][ri][c];
            }
}

// ---------------------------------------------------------------------------
// Head: one row per warp; down-proj via 8-lane groups (24 shuffles/row);
// then thread-per-column projection over the CTA's 8 rows.
// grid 256 x 256 threads.
// ---------------------------------------------------------------------------
#define HB 8
__global__ __launch_bounds__(256) void head_kernel(
    const int* __restrict__ lang_ids,
    const float* __restrict__ down_w, const float* __restrict__ down_b,
    const float* __restrict__ up_b,
    const float* __restrict__ ln_g,   const float* __restrict__ ln_b,
    const float* __restrict__ proj_w, const float* __restrict__ proj_b,
    float* __restrict__ out) {
    __shared__ float y_s[HB][EE];
    const int tid = threadIdx.x, w = tid >> 5, lane = tid & 31;
    const int b0 = blockIdx.x * HB;
    const int b = b0 + w;
    const int l = lang_ids[b];
    const float* fb = g_feat + b * EE;

    // feat in grouped pattern: lane covers elems (lane&7)*4 + 32c
    float4 f4[8];
    #pragma unroll
    for (int c = 0; c < 8; c++)
        f4[c] = *(const float4*)(fb + (lane & 7) * 4 + 32 * c);

    // down-proj: 8 groups of 4 units, 8 lanes per unit
    float hid = 0.0f;
    const float* dwb = down_w + l * BNK * EE;
    #pragma unroll
    for (int g = 0; g < 8; g++) {
        const int d = 4 * g + (lane >> 3);
        const float* wr = dwb + d * EE + (lane & 7) * 4;
        float s = 0.0f;
        #pragma unroll
        for (int c = 0; c < 8; c++) {
            float4 wv = *(const float4*)(wr + 32 * c);
            s = fmaf(f4[c].x, wv.x, s); s = fmaf(f4[c].y, wv.y, s);
            s = fmaf(f4[c].z, wv.z, s); s = fmaf(f4[c].w, wv.w, s);
        }
        s += __shfl_xor_sync(0xffffffffu, s, 1);
        s += __shfl_xor_sync(0xffffffffu, s, 2);
        s += __shfl_xor_sync(0xffffffffu, s, 4);
        float got = __shfl_sync(0xffffffffu, s, (lane & 3) * 8);
        if ((lane >> 2) == g) hid = got;
    }
    hid += down_b[l * BNK + lane];
    hid = 0.5f * hid * (1.0f + erff(hid * 0.7071067811865476f));

    // up-proj (transposed weights) + residual + LN
    const float4 fx0 = *(const float4*)(fb + lane * 8);
    const float4 fx1 = *(const float4*)(fb + lane * 8 + 4);
    float4 a0 = *(const float4*)(up_b + l * EE + lane * 8);
    float4 a1 = *(const float4*)(up_b + l * EE + lane * 8 + 4);
    const float* uwb = g_upwT + l * BNK * EE;
    #pragma unroll 4
    for (int d = 0; d < BNK; d++) {
        float hd = __shfl_sync(0xffffffffu, hid, d);
        float4 u0 = *(const float4*)(uwb + d * EE + lane * 8);
        float4 u1 = *(const float4*)(uwb + d * EE + lane * 8 + 4);
        a0.x = fmaf(hd, u0.x, a0.x); a0.y = fmaf(hd, u0.y, a0.y);
        a0.z = fmaf(hd, u0.z, a0.z); a0.w = fmaf(hd, u0.w, a0.w);
        a1.x = fmaf(hd, u1.x, a1.x); a1.y = fmaf(hd, u1.y, a1.y);
        a1.z = fmaf(hd, u1.z, a1.z); a1.w = fmaf(hd, u1.w, a1.w);
    }
    float x[8] = {fx0.x + a0.x, fx0.y + a0.y, fx0.z + a0.z, fx0.w + a0.w,
                  fx1.x + a1.x, fx1.y + a1.y, fx1.z + a1.z, fx1.w + a1.w};
    float s1 = 0.0f, s2 = 0.0f;
    #pragma unroll
    for (int j = 0; j < 8; j++) { s1 += x[j]; s2 = fmaf(x[j], x[j], s2); }
    #pragma unroll
    for (int o = 16; o; o >>= 1) {
        s1 += __shfl_xor_sync(0xffffffffu, s1, o);
        s2 += __shfl_xor_sync(0xffffffffu, s2, o);
    }
    const float mu = s1 * (1.0f / EE);
    const float rstd = rsqrtf(s2 * (1.0f / EE) - mu * mu + 1e-5f);
    const float4 g0 = *(const float4*)(ln_g + l * EE + lane * 8);
    const float4 g1 = *(const float4*)(ln_g + l * EE + lane * 8 + 4);
    const float4 bb0 = *(const float4*)(ln_b + l * EE + lane * 8);
    const float4 bb1 = *(const float4*)(ln_b + l * EE + lane * 8 + 4);
    float4 y0, y1;
    y0.x = (x[0]-mu)*rstd*g0.x + bb0.x;  y0.y = (x[1]-mu)*rstd*g0.y + bb0.y;
    y0.z = (x[2]-mu)*rstd*g0.z + bb0.z;  y0.w = (x[3]-mu)*rstd*g0.w + bb0.w;
    y1.x = (x[4]-mu)*rstd*g1.x + bb1.x;  y1.y = (x[5]-mu)*rstd*g1.y + bb1.y;
    y1.z = (x[6]-mu)*rstd*g1.z + bb1.z;  y1.w = (x[7]-mu)*rstd*g1.w + bb1.w;
    *(float4*)(&y_s[w][lane * 8])     = y0;
    *(float4*)(&y_s[w][lane * 8 + 4]) = y1;
    __syncthreads();

    // projection: thread owns output column `tid` for the CTA's 8 rows
    float accv[HB];
    #pragma unroll
    for (int r = 0; r < HB; r++) accv[r] = proj_b[tid];
    const float* pw = proj_w + tid * EE;
    for (int e = 0; e < EE; e += 4) {
        float4 wv = *(const float4*)(pw + e);
        #pragma unroll
        for (int r = 0; r < HB; r++) {
            float4 yv = *(const float4*)(&y_s[r][e]);
            accv[r] = fmaf(wv.x, yv.x, accv[r]);
            accv[r] = fmaf(wv.y, yv.y, accv[r]);
            accv[r] = fmaf(wv.z, yv.z, accv[r]);
            accv[r] = fmaf(wv.w, yv.w, accv[r]);
        }
    }
    #pragma unroll
    for (int r = 0; r < HB; r++) out[(b0 + r) * OO + tid] = accv[r];
}

// ---------------------------------------------------------------------------
extern "C" void kernel_launch(void* const* d_in, const int* in_sizes, int n_in,
                              void* d_out, int out_size) {
    const int*   tokens = (const int*)d_in[0];
    const int*   lang   = (const int*)d_in[1];
    const float* ce     = (const float*)d_in[2];
    const float* wih_f  = (const float*)d_in[3];
    const float* whh_f  = (const float*)d_in[4];
    const float* bih_f  = (const float*)d_in[5];
    const float* bhh_f  = (const float*)d_in[6];
    const float* wih_b  = (const float*)d_in[7];
    const float* whh_b  = (const float*)d_in[8];
    const float* bih_b  = (const float*)d_in[9];
    const float* bhh_b  = (const float*)d_in[10];
    const float* down_w = (const float*)d_in[11];
    const float* down_b = (const float*)d_in[12];
    const float* up_w   = (const float*)d_in[13];
    const float* up_b   = (const float*)d_in[14];
    const float* ln_g   = (const float*)d_in[15];
    const float* ln_b   = (const float*)d_in[16];
    const float* proj_w = (const float*)d_in[17];
    const float* proj_b = (const float*)d_in[18];
    float* out = (float*)d_out;

    cudaFuncSetAttribute(gru_mma_kernel,
                         cudaFuncAttributeMaxDynamicSharedMemorySize, SMEM_TOTAL);
    const size_t xsmem = (size_t)(GG * CC + GG + 32 * CC) * sizeof(float);
    cudaFuncSetAttribute(xtab_kernel,
                         cudaFuncAttributeMaxDynamicSharedMemorySize, (int)xsmem);

    wsplit_kernel<<<dim3(2, GG), HH>>>(whh_f, whh_b);
    xtab_kernel<<<dim3(8, 2), GG, xsmem>>>(ce, wih_f, bih_f, wih_b, bih_b);
    upwT_kernel<<<96, 256>>>(up_w);
    gru_mma_kernel<<<dim3(BATCH / BM, 2), NTH, SMEM_TOTAL>>>(tokens, bhh_f, bhh_b);
    head_kernel<<<BATCH / HB, 256>>>(lang, down_w, down_b, up_b,
                                     ln_g, ln_b, proj_w, proj_b, out);
}

// round 5
// speedup vs baseline: 5.0813x; 1.5068x over previous
#include <cuda_runtime.h>
#include <cuda_fp16.h>
#include <cuda_bf16.h>
#include <math.h>
#include <stdint.h>

// Problem dims
#define BATCH 2048
#define TT    128
#define VV    256
#define CC    32
#define HH    128
#define EE    256
#define GG    384   // 3*H
#define OO    256
#define NLN   3
#define BNK   32

// GRU tiling
#define BM    32      // batch rows per CTA (2 streams x 16)
#define NTH   512     // 16 warps, 24 gate-cols each
// SMEM byte offsets
#define SW0   0                   // w fp16: [384][128] half, swizzled (96KB)
#define SH16(s) (98304 + (s) * 4096)   // h fp16 per stream [16][128]
#define SMEM_TOTAL 106496

// Scratch (static device globals)
__device__ __align__(16) __half g_w0[2 * GG * HH];  // [dir][p][k] fp16
__device__ float g_xtab[2 * VV * GG];   // permuted (x @ w_ih^T + b_ih) per dir
__device__ float g_feat[BATCH * EE];
__device__ float g_upwT[NLN * BNK * EE]; // up_w transposed: [l][d][e]

// ---------------------------------------------------------------------------
// MUFU sigmoid/tanh: sigm(x) = e^x / (1 + e^x)  (exact identity, all x).
// ---------------------------------------------------------------------------
__device__ __forceinline__ float sigm(float x) {
    float t = fminf(x * 1.4426950408889634f, 80.0f);
    float e; asm("ex2.approx.f32 %0, %1;" : "=f"(e) : "f"(t));
    float d = 1.0f + e;
    float y; asm("rcp.approx.f32 %0, %1;" : "=f"(y) : "f"(d));
    y = y * fmaf(-d, y, 2.0f);
    return e * y;
}
__device__ __forceinline__ float tanh_(float x) {
    return fmaf(2.0f, sigm(2.0f * x), -1.0f);
}

// ---------------------------------------------------------------------------
// MMA / ldmatrix wrappers
// ---------------------------------------------------------------------------
__device__ __forceinline__ void ldsm4(uint32_t& r0, uint32_t& r1, uint32_t& r2,
                                      uint32_t& r3, uint32_t addr) {
    asm volatile("ldmatrix.sync.aligned.m8n8.x4.shared.b16 {%0,%1,%2,%3}, [%4];"
                 : "=r"(r0), "=r"(r1), "=r"(r2), "=r"(r3) : "r"(addr));
}
__device__ __forceinline__ void mma16816(float* d, const uint32_t* a,
                                         uint32_t b0, uint32_t b1) {
    asm volatile(
        "mma.sync.aligned.m16n8k16.row.col.f32.f16.f16.f32 "
        "{%0,%1,%2,%3}, {%4,%5,%6,%7}, {%8,%9}, {%0,%1,%2,%3};"
        : "+f"(d[0]), "+f"(d[1]), "+f"(d[2]), "+f"(d[3])
        : "r"(a[0]), "r"(a[1]), "r"(a[2]), "r"(a[3]), "r"(b0), "r"(b1));
}

// gate-dim permutation for 16 warps (24 cols each):
// orig g = t*128 + j  ->  p = 24*(j>>3) + 8*t + (j&7)
__device__ __forceinline__ int permute_g(int g) {
    int t = g >> 7, j = g & 127;
    return 24 * (j >> 3) + 8 * t + (j & 7);
}

// ---------------------------------------------------------------------------
// Prep A: xtab (permuted), w_ih staged in SMEM. grid (8, 2) x 384.
// ---------------------------------------------------------------------------
__global__ void xtab_kernel(const float* __restrict__ ce,
                            const float* __restrict__ wih_f, const float* __restrict__ bih_f,
                            const float* __restrict__ wih_b, const float* __restrict__ bih_b) {
    extern __shared__ float xsm[];
    float* ws = xsm;               // [384*32]
    float* bs = ws + GG * CC;      // [384]
    float* cs = bs + GG;           // [32*32]
    const int d = blockIdx.y, g = threadIdx.x;
    const float* wih = d ? wih_b : wih_f;
    const float* bih = d ? bih_b : bih_f;
    for (int i = g; i < GG * CC; i += GG) ws[i] = wih[i];
    bs[g] = bih[g];
    const int v0 = blockIdx.x * 32;
    for (int i = g; i < 32 * CC; i += GG) cs[i] = ce[v0 * CC + i];
    __syncthreads();
    const int p = permute_g(g);
    for (int vi = 0; vi < 32; vi++) {
        float s = bs[g];
        #pragma unroll
        for (int c = 0; c < CC; c++) s = fmaf(cs[vi * CC + c], ws[g * CC + c], s);
        g_xtab[(d * VV + v0 + vi) * GG + p] = s;
    }
}

// ---------------------------------------------------------------------------
// Prep B: w_hh fp16 (round-to-nearest), permuted. grid (2, 384) x 128.
// ---------------------------------------------------------------------------
__global__ void wsplit_kernel(const float* __restrict__ whh_f,
                              const float* __restrict__ whh_b) {
    const int d = blockIdx.x, g = blockIdx.y, k = threadIdx.x;
    const float* w = d ? whh_b : whh_f;
    const int p = permute_g(g);
    g_w0[d * GG * HH + p * HH + k] = __float2half_rn(w[g * HH + k]);
}

// ---------------------------------------------------------------------------
// Prep C: transpose up_w [l][e][d] -> [l][d][e].
// ---------------------------------------------------------------------------
__global__ void upwT_kernel(const float* __restrict__ up_w) {
    for (int i = blockIdx.x * 256 + threadIdx.x; i < NLN * EE * BNK;
         i += gridDim.x * 256) {
        int l = i / (EE * BNK), rem = i % (EE * BNK);
        int e = rem / BNK, dd = rem % BNK;
        g_upwT[(l * BNK + dd) * EE + e] = up_w[i];
    }
}

// ---------------------------------------------------------------------------
// GRU via mma (fp16 operands, fp32 accum and fp32 register-resident hprev).
// 16 warps, gate cells interleaved into the mma k-loop. grid (64, 2) x 512.
// ---------------------------------------------------------------------------
__global__ __launch_bounds__(NTH, 1) void gru_mma_kernel(
    const int* __restrict__ tokens,
    const float* __restrict__ bhh_f, const float* __restrict__ bhh_b) {
    extern __shared__ __align__(16) char smem[];
    const uint32_t sb = (uint32_t)__cvta_generic_to_shared(smem);

    const int dir  = blockIdx.y;
    const int b0r  = blockIdx.x * BM;
    const int tid  = threadIdx.x;
    const int w    = tid >> 5;      // 0..15
    const int lane = tid & 31;
    const int lr   = lane >> 2;     // 0..7
    const int lq   = lane & 3;      // 0..3

    const float* bhh = dir ? bhh_b : bhh_f;
    const float* xt  = g_xtab + dir * VV * GG;

    // ---- load w (swizzled) + zero h buffers ----
    {
        const uint4* gw0 = (const uint4*)(g_w0 + dir * (GG * HH));
        for (int idx = tid; idx < GG * 16; idx += NTH) {
            int n = idx >> 4, c = idx & 15;
            int off = n * 256 + ((c ^ (n & 7)) << 4);
            *(uint4*)(smem + SW0 + off) = gw0[idx];
        }
        for (int idx = tid; idx < 512; idx += NTH)
            ((uint4*)(smem + SH16(0)))[idx] = make_uint4(0, 0, 0, 0);
    }

    // biases for this thread's 2 gate columns (j = 8w + 2lq + {0,1})
    float bias[3][2];
    #pragma unroll
    for (int t = 0; t < 3; t++)
        #pragma unroll
        for (int c = 0; c < 2; c++)
            bias[t][c] = bhh[t * 128 + 8 * w + 2 * lq + c];

    // ldmatrix addressing constants
    const int ar  = lane & 15;
    const int ahi = lane >> 4;
    const int asw = ar & 7;
    const int bj  = lane >> 3;
    const int bsw = lane & 7;
    const int brow = (24 * w + (lane & 7)) * 256;

    // h' store offsets (chunk index = w since unit j = 8w + ..)
    int stoff[2];
    #pragma unroll
    for (int ri = 0; ri < 2; ri++)
        stoff[ri] = (lr + 8 * ri) * 256 + ((w ^ lr) << 4) + 4 * lq;

    float hprev[2][2][2];
    float acc[2][3][4];
    #pragma unroll
    for (int s = 0; s < 2; s++) {
        #pragma unroll
        for (int ri = 0; ri < 2; ri++)
            #pragma unroll
            for (int c = 0; c < 2; c++) hprev[s][ri][c] = 0.0f;
        #pragma unroll
        for (int nt = 0; nt < 3; nt++)
            #pragma unroll
            for (int rg = 0; rg < 4; rg++)
                acc[s][nt][rg] = bias[nt][rg & 1];
    }

    __syncthreads();

    #pragma unroll 1
    for (int t = 0; t < TT; t++) {
        const int tcol = dir ? (TT - 1 - t) : t;

        // xp gather for both streams (L2 table; consumed in gate cells)
        float2 xp[2][2][3];
        #pragma unroll
        for (int s = 0; s < 2; s++)
            #pragma unroll
            for (int ri = 0; ri < 2; ri++) {
                int tok = tokens[(b0r + 16 * s + lr + 8 * ri) * TT + tcol];
                const float2* xr = (const float2*)(xt + tok * GG + 24 * w);
                #pragma unroll
                for (int u = 0; u < 3; u++)
                    xp[s][ri][u] = xr[4 * u + lq];
            }

        #pragma unroll
        for (int ph = 0; ph < 2; ph++) {
            const int sm_ = 1 - ph;   // mma stream
            const int sg  = ph;       // gate stream

            // reset mma-stream accumulators to bias
            #pragma unroll
            for (int nt = 0; nt < 3; nt++)
                #pragma unroll
                for (int rg = 0; rg < 4; rg++)
                    acc[sm_][nt][rg] = bias[nt][rg & 1];

            const bool do_mma = ph ? (t < TT - 1) : (t > 0);
            const uint32_t ab0 = sb + SH16(sm_) + ar * 256;

            #pragma unroll
            for (int kc2 = 0; kc2 < 4; kc2++) {
                uint32_t a0[8];
                if (do_mma) {
                    uint32_t clo = (uint32_t)(((4 * kc2 + ahi) ^ asw) << 4);
                    uint32_t chi = (uint32_t)(((4 * kc2 + 2 + ahi) ^ asw) << 4);
                    ldsm4(a0[0], a0[1], a0[2], a0[3], ab0 + clo);
                    ldsm4(a0[4], a0[5], a0[6], a0[7], ab0 + chi);
                }

                // one gate cell of the gate stream, interleaved with mma
                {
                    const int ri = kc2 >> 1, c01 = kc2 & 1, rg = 2 * ri + c01;
                    float xr_ = (c01 ? xp[sg][ri][0].y : xp[sg][ri][0].x)
                                + acc[sg][0][rg];
                    float xz_ = (c01 ? xp[sg][ri][1].y : xp[sg][ri][1].x)
                                + acc[sg][1][rg];
                    float xn_ = (c01 ? xp[sg][ri][2].y : xp[sg][ri][2].x);
                    float nh  = acc[sg][2][rg];
                    float r = sigm(xr_);
                    float z = sigm(xz_);
                    float n = tanh_(fmaf(r, nh, xn_));
                    float h = fmaf(z, hprev[sg][ri][c01] - n, n);
                    hprev[sg][ri][c01] = h;
                    *(__half*)(smem + SH16(sg) + stoff[ri] + 2 * c01) =
                        __float2half_rn(h);
                }

                if (do_mma) {
                    const uint32_t chunk = (uint32_t)(((4 * kc2 + bj) ^ bsw) << 4);
                    #pragma unroll
                    for (int nt = 0; nt < 3; nt++) {
                        uint32_t bh[4];
                        ldsm4(bh[0], bh[1], bh[2], bh[3],
                              sb + SW0 + brow + nt * 2048 + chunk);
                        mma16816(acc[sm_][nt], a0 + 0, bh[0], bh[1]);
                        mma16816(acc[sm_][nt], a0 + 4, bh[2], bh[3]);
                    }
                }
            }
            __syncthreads();
        }
    }

    // final hidden -> feat
    #pragma unroll
    for (int s = 0; s < 2; s++)
        #pragma unroll
        for (int ri = 0; ri < 2; ri++)
            #pragma unroll
            for (int c = 0; c < 2; c++) {
                int m = 16 * s + lr + 8 * ri;
                int j = 8 * w + 2 * lq + c;
                g_feat[(b0r + m) * EE + dir * HH + j] = hprev[s][ri][c];
            }
}

// ---------------------------------------------------------------------------
// Head: one row per warp; down-proj via 8-lane groups; then thread-per-column
// projection over the CTA's 8 rows. grid 256 x 256 threads.
// ---------------------------------------------------------------------------
#define HB 8
__global__ __launch_bounds__(256) void head_kernel(
    const int* __restrict__ lang_ids,
    const float* __restrict__ down_w, const float* __restrict__ down_b,
    const float* __restrict__ up_b,
    const float* __restrict__ ln_g,   const float* __restrict__ ln_b,
    const float* __restrict__ proj_w, const float* __restrict__ proj_b,
    float* __restrict__ out) {
    __shared__ float y_s[HB][EE];
    const int tid = threadIdx.x, w = tid >> 5, lane = tid & 31;
    const int b0 = blockIdx.x * HB;
    const int b = b0 + w;
    const int l = lang_ids[b];
    const float* fb = g_feat + b * EE;

    // feat in grouped pattern: lane covers elems (lane&7)*4 + 32c
    float4 f4[8];
    #pragma unroll
    for (int c = 0; c < 8; c++)
        f4[c] = *(const float4*)(fb + (lane & 7) * 4 + 32 * c);

    // down-proj: 8 groups of 4 units, 8 lanes per unit
    float hid = 0.0f;
    const float* dwb = down_w + l * BNK * EE;
    #pragma unroll
    for (int g = 0; g < 8; g++) {
        const int d = 4 * g + (lane >> 3);
        const float* wr = dwb + d * EE + (lane & 7) * 4;
        float s = 0.0f;
        #pragma unroll
        for (int c = 0; c < 8; c++) {
            float4 wv = *(const float4*)(wr + 32 * c);
            s = fmaf(f4[c].x, wv.x, s); s = fmaf(f4[c].y, wv.y, s);
            s = fmaf(f4[c].z, wv.z, s); s = fmaf(f4[c].w, wv.w, s);
        }
        s += __shfl_xor_sync(0xffffffffu, s, 1);
        s += __shfl_xor_sync(0xffffffffu, s, 2);
        s += __shfl_xor_sync(0xffffffffu, s, 4);
        float got = __shfl_sync(0xffffffffu, s, (lane & 3) * 8);
        if ((lane >> 2) == g) hid = got;
    }
    hid += down_b[l * BNK + lane];
    hid = 0.5f * hid * (1.0f + erff(hid * 0.7071067811865476f));

    // up-proj (transposed weights) + residual + LN
    const float4 fx0 = *(const float4*)(fb + lane * 8);
    const float4 fx1 = *(const float4*)(fb + lane * 8 + 4);
    float4 a0 = *(const float4*)(up_b + l * EE + lane * 8);
    float4 a1 = *(const float4*)(up_b + l * EE + lane * 8 + 4);
    const float* uwb = g_upwT + l * BNK * EE;
    #pragma unroll 4
    for (int d = 0; d < BNK; d++) {
        float hd = __shfl_sync(0xffffffffu, hid, d);
        float4 u0 = *(const float4*)(uwb + d * EE + lane * 8);
        float4 u1 = *(const float4*)(uwb + d * EE + lane * 8 + 4);
        a0.x = fmaf(hd, u0.x, a0.x); a0.y = fmaf(hd, u0.y, a0.y);
        a0.z = fmaf(hd, u0.z, a0.z); a0.w = fmaf(hd, u0.w, a0.w);
        a1.x = fmaf(hd, u1.x, a1.x); a1.y = fmaf(hd, u1.y, a1.y);
        a1.z = fmaf(hd, u1.z, a1.z); a1.w = fmaf(hd, u1.w, a1.w);
    }
    float x[8] = {fx0.x + a0.x, fx0.y + a0.y, fx0.z + a0.z, fx0.w + a0.w,
                  fx1.x + a1.x, fx1.y + a1.y, fx1.z + a1.z, fx1.w + a1.w};
    float s1 = 0.0f, s2 = 0.0f;
    #pragma unroll
    for (int j = 0; j < 8; j++) { s1 += x[j]; s2 = fmaf(x[j], x[j], s2); }
    #pragma unroll
    for (int o = 16; o; o >>= 1) {
        s1 += __shfl_xor_sync(0xffffffffu, s1, o);
        s2 += __shfl_xor_sync(0xffffffffu, s2, o);
    }
    const float mu = s1 * (1.0f / EE);
    const float rstd = rsqrtf(s2 * (1.0f / EE) - mu * mu + 1e-5f);
    const float4 g0 = *(const float4*)(ln_g + l * EE + lane * 8);
    const float4 g1 = *(const float4*)(ln_g + l * EE + lane * 8 + 4);
    const float4 bb0 = *(const float4*)(ln_b + l * EE + lane * 8);
    const float4 bb1 = *(const float4*)(ln_b + l * EE + lane * 8 + 4);
    float4 y0, y1;
    y0.x = (x[0]-mu)*rstd*g0.x + bb0.x;  y0.y = (x[1]-mu)*rstd*g0.y + bb0.y;
    y0.z = (x[2]-mu)*rstd*g0.z + bb0.z;  y0.w = (x[3]-mu)*rstd*g0.w + bb0.w;
    y1.x = (x[4]-mu)*rstd*g1.x + bb1.x;  y1.y = (x[5]-mu)*rstd*g1.y + bb1.y;
    y1.z = (x[6]-mu)*rstd*g1.z + bb1.z;  y1.w = (x[7]-mu)*rstd*g1.w + bb1.w;
    *(float4*)(&y_s[w][lane * 8])     = y0;
    *(float4*)(&y_s[w][lane * 8 + 4]) = y1;
    __syncthreads();

    // projection: thread owns output column `tid` for the CTA's 8 rows
    float accv[HB];
    #pragma unroll
    for (int r = 0; r < HB; r++) accv[r] = proj_b[tid];
    const float* pw = proj_w + tid * EE;
    for (int e = 0; e < EE; e += 4) {
        float4 wv = *(const float4*)(pw + e);
        #pragma unroll
        for (int r = 0; r < HB; r++) {
            float4 yv = *(const float4*)(&y_s[r][e]);
            accv[r] = fmaf(wv.x, yv.x, accv[r]);
            accv[r] = fmaf(wv.y, yv.y, accv[r]);
            accv[r] = fmaf(wv.z, yv.z, accv[r]);
            accv[r] = fmaf(wv.w, yv.w, accv[r]);
        }
    }
    #pragma unroll
    for (int r = 0; r < HB; r++) out[(b0 + r) * OO + tid] = accv[r];
}

// ---------------------------------------------------------------------------
extern "C" void kernel_launch(void* const* d_in, const int* in_sizes, int n_in,
                              void* d_out, int out_size) {
    const int*   tokens = (const int*)d_in[0];
    const int*   lang   = (const int*)d_in[1];
    const float* ce     = (const float*)d_in[2];
    const float* wih_f  = (const float*)d_in[3];
    const float* whh_f  = (const float*)d_in[4];
    const float* bih_f  = (const float*)d_in[5];
    const float* bhh_f  = (const float*)d_in[6];
    const float* wih_b  = (const float*)d_in[7];
    const float* whh_b  = (const float*)d_in[8];
    const float* bih_b  = (const float*)d_in[9];
    const float* bhh_b  = (const float*)d_in[10];
    const float* down_w = (const float*)d_in[11];
    const float* down_b = (const float*)d_in[12];
    const float* up_w   = (const float*)d_in[13];
    const float* up_b   = (const float*)d_in[14];
    const float* ln_g   = (const float*)d_in[15];
    const float* ln_b   = (const float*)d_in[16];
    const float* proj_w = (const float*)d_in[17];
    const float* proj_b = (const float*)d_in[18];
    float* out = (float*)d_out;

    cudaFuncSetAttribute(gru_mma_kernel,
                         cudaFuncAttributeMaxDynamicSharedMemorySize, SMEM_TOTAL);
    const size_t xsmem = (size_t)(GG * CC + GG + 32 * CC) * sizeof(float);
    cudaFuncSetAttribute(xtab_kernel,
                         cudaFuncAttributeMaxDynamicSharedMemorySize, (int)xsmem);

    wsplit_kernel<<<dim3(2, GG), HH>>>(whh_f, whh_b);
    xtab_kernel<<<dim3(8, 2), GG, xsmem>>>(ce, wih_f, bih_f, wih_b, bih_b);
    upwT_kernel<<<96, 256>>>(up_w);
    gru_mma_kernel<<<dim3(BATCH / BM, 2), NTH, SMEM_TOTAL>>>(tokens, bhh_f, bhh_b);
    head_kernel<<<BATCH / HB, 256>>>(lang, down_w, down_b, up_b,
                                     ln_g, ln_b, proj_w, proj_b, out);
}

// round 6
// speedup vs baseline: 6.0169x; 1.1841x over previous
#include <cuda_runtime.h>
#include <cuda_fp16.h>
#include <cuda_bf16.h>
#include <math.h>
#include <stdint.h>

// Problem dims
#define BATCH 2048
#define TT    128
#define VV    256
#define CC    32
#define HH    128
#define EE    256
#define GG    384   // 3*H
#define OO    256
#define NLN   3
#define BNK   32

// GRU tiling
#define BM    32      // batch rows per CTA (2 streams x 16)
#define NTH   512     // 16 warps, 24 gate-cols each
// SMEM byte offsets
#define SW0   0                   // w fp16: [384][128] half, swizzled (96KB)
#define SH16(s) (98304 + (s) * 4096)   // h fp16 per stream [16][128]
#define SMEM_TOTAL 106496

// Scratch (static device globals)
__device__ __align__(16) __half g_w0[2 * GG * HH];  // [dir][p][k] fp16
__device__ float g_xtab[2 * VV * GG];   // permuted x@w_ih^T + b_ih (+b_hh r,z)
__device__ float g_feat[BATCH * EE];
__device__ float g_upwT[NLN * BNK * EE]; // up_w transposed: [l][d][e]
__device__ int   g_tokT[TT * BATCH];     // tokens transposed [t][b]

// ---------------------------------------------------------------------------
// Activations. Precise path (ex2+rcp+Newton) for n; HW tanh for r/z sigmoids.
// ---------------------------------------------------------------------------
__device__ __forceinline__ float sigm_precise(float x) {
    float t = fminf(x * 1.4426950408889634f, 80.0f);
    float e; asm("ex2.approx.f32 %0, %1;" : "=f"(e) : "f"(t));
    float d = 1.0f + e;
    float y; asm("rcp.approx.f32 %0, %1;" : "=f"(y) : "f"(d));
    y = y * fmaf(-d, y, 2.0f);
    return e * y;
}
__device__ __forceinline__ float tanh_precise(float x) {
    return fmaf(2.0f, sigm_precise(2.0f * x), -1.0f);
}
__device__ __forceinline__ float tanh_hw(float x) {
    float y; asm("tanh.approx.f32 %0, %1;" : "=f"(y) : "f"(x));
    return y;
}
__device__ __forceinline__ float sigm_fast(float x) {   // 1 MUFU + 2 FMA-class
    return fmaf(tanh_hw(0.5f * x), 0.5f, 0.5f);
}

// ---------------------------------------------------------------------------
// MMA / ldmatrix wrappers
// ---------------------------------------------------------------------------
__device__ __forceinline__ void ldsm4(uint32_t& r0, uint32_t& r1, uint32_t& r2,
                                      uint32_t& r3, uint32_t addr) {
    asm volatile("ldmatrix.sync.aligned.m8n8.x4.shared.b16 {%0,%1,%2,%3}, [%4];"
                 : "=r"(r0), "=r"(r1), "=r"(r2), "=r"(r3) : "r"(addr));
}
__device__ __forceinline__ void mma16816(float* d, const uint32_t* a,
                                         uint32_t b0, uint32_t b1) {
    asm volatile(
        "mma.sync.aligned.m16n8k16.row.col.f32.f16.f16.f32 "
        "{%0,%1,%2,%3}, {%4,%5,%6,%7}, {%8,%9}, {%0,%1,%2,%3};"
        : "+f"(d[0]), "+f"(d[1]), "+f"(d[2]), "+f"(d[3])
        : "r"(a[0]), "r"(a[1]), "r"(a[2]), "r"(a[3]), "r"(b0), "r"(b1));
}

// gate-dim permutation for 16 warps (24 cols each):
// orig g = t*128 + j  ->  p = 24*(j>>3) + 8*t + (j&7)
__device__ __forceinline__ int permute_g(int g) {
    int t = g >> 7, j = g & 127;
    return 24 * (j >> 3) + 8 * t + (j & 7);
}

// ---------------------------------------------------------------------------
// Prep A: xtab (permuted). b_ih always; b_hh folded for r,z gates only
// (b_hh_n is multiplied by r inside the cell, so it stays separate).
// ---------------------------------------------------------------------------
__global__ void xtab_kernel(const float* __restrict__ ce,
                            const float* __restrict__ wih_f, const float* __restrict__ bih_f,
                            const float* __restrict__ wih_b, const float* __restrict__ bih_b,
                            const float* __restrict__ bhh_f, const float* __restrict__ bhh_b) {
    extern __shared__ float xsm[];
    float* ws = xsm;               // [384*32]
    float* bs = ws + GG * CC;      // [384]
    float* cs = bs + GG;           // [32*32]
    const int d = blockIdx.y, g = threadIdx.x;
    const float* wih = d ? wih_b : wih_f;
    const float* bih = d ? bih_b : bih_f;
    const float* bhh = d ? bhh_b : bhh_f;
    for (int i = g; i < GG * CC; i += GG) ws[i] = wih[i];
    bs[g] = bih[g] + (g < 2 * HH ? bhh[g] : 0.0f);
    const int v0 = blockIdx.x * 32;
    for (int i = g; i < 32 * CC; i += GG) cs[i] = ce[v0 * CC + i];
    __syncthreads();
    const int p = permute_g(g);
    for (int vi = 0; vi < 32; vi++) {
        float s = bs[g];
        #pragma unroll
        for (int c = 0; c < CC; c++) s = fmaf(cs[vi * CC + c], ws[g * CC + c], s);
        g_xtab[(d * VV + v0 + vi) * GG + p] = s;
    }
}

// ---------------------------------------------------------------------------
// Prep B: w_hh fp16, permuted. grid (2, 384) x 128.
// ---------------------------------------------------------------------------
__global__ void wsplit_kernel(const float* __restrict__ whh_f,
                              const float* __restrict__ whh_b) {
    const int d = blockIdx.x, g = blockIdx.y, k = threadIdx.x;
    const float* w = d ? whh_b : whh_f;
    const int p = permute_g(g);
    g_w0[d * GG * HH + p * HH + k] = __float2half_rn(w[g * HH + k]);
}

// ---------------------------------------------------------------------------
// Prep C: transpose up_w; Prep D: transpose tokens.
// ---------------------------------------------------------------------------
__global__ void upwT_kernel(const float* __restrict__ up_w) {
    for (int i = blockIdx.x * 256 + threadIdx.x; i < NLN * EE * BNK;
         i += gridDim.x * 256) {
        int l = i / (EE * BNK), rem = i % (EE * BNK);
        int e = rem / BNK, dd = rem % BNK;
        g_upwT[(l * BNK + dd) * EE + e] = up_w[i];
    }
}
__global__ void tokT_kernel(const int* __restrict__ tokens) {
    int i = blockIdx.x * 256 + threadIdx.x;
    if (i < BATCH * TT) {
        int b = i / TT, t = i % TT;
        g_tokT[t * BATCH + b] = tokens[i];
    }
}

// ---------------------------------------------------------------------------
// GRU via mma (fp16 operands, fp32 accum + fp32 register hprev).
// B-frags for gate groups 0,1 cached in registers across all 128 steps.
// grid (64, 2) x 512 threads.
// ---------------------------------------------------------------------------
__global__ __launch_bounds__(NTH, 1) void gru_mma_kernel(
    const float* __restrict__ bhh_f, const float* __restrict__ bhh_b) {
    extern __shared__ __align__(16) char smem[];
    const uint32_t sb = (uint32_t)__cvta_generic_to_shared(smem);

    const int dir  = blockIdx.y;
    const int b0r  = blockIdx.x * BM;
    const int tid  = threadIdx.x;
    const int w    = tid >> 5;      // 0..15
    const int lane = tid & 31;
    const int lr   = lane >> 2;     // 0..7
    const int lq   = lane & 3;      // 0..3

    const float* bhh = dir ? bhh_b : bhh_f;
    const float* xt  = g_xtab + dir * VV * GG;

    // ---- load w (swizzled) + zero h buffers ----
    {
        const uint4* gw0 = (const uint4*)(g_w0 + dir * (GG * HH));
        for (int idx = tid; idx < GG * 16; idx += NTH) {
            int n = idx >> 4, c = idx & 15;
            int off = n * 256 + ((c ^ (n & 7)) << 4);
            *(uint4*)(smem + SW0 + off) = gw0[idx];
        }
        for (int idx = tid; idx < 512; idx += NTH)
            ((uint4*)(smem + SH16(0)))[idx] = make_uint4(0, 0, 0, 0);
    }

    // n-gate bias only (r,z folded into xtab)
    float bias_n[2];
    #pragma unroll
    for (int c = 0; c < 2; c++)
        bias_n[c] = bhh[2 * 128 + 8 * w + 2 * lq + c];

    // ldmatrix addressing constants
    const int ar  = lane & 15;
    const int ahi = lane >> 4;
    const int asw = ar & 7;
    const int bj  = lane >> 3;
    const int bsw = lane & 7;
    const int brow = (24 * w + (lane & 7)) * 256;

    // h' store offsets
    int stoff[2];
    #pragma unroll
    for (int ri = 0; ri < 2; ri++)
        stoff[ri] = (lr + 8 * ri) * 256 + ((w ^ lr) << 4) + 4 * lq;

    __syncthreads();

    // ---- cache B fragments for gate groups nt=0,1 (loop-invariant) ----
    uint32_t Brg[2][4][4];
    #pragma unroll
    for (int nt = 0; nt < 2; nt++)
        #pragma unroll
        for (int kc2 = 0; kc2 < 4; kc2++) {
            uint32_t chunk = (uint32_t)(((4 * kc2 + bj) ^ bsw) << 4);
            ldsm4(Brg[nt][kc2][0], Brg[nt][kc2][1], Brg[nt][kc2][2],
                  Brg[nt][kc2][3], sb + SW0 + brow + nt * 2048 + chunk);
        }

    float hprev[2][2][2];
    float acc[2][3][4];
    #pragma unroll
    for (int s = 0; s < 2; s++) {
        #pragma unroll
        for (int ri = 0; ri < 2; ri++)
            #pragma unroll
            for (int c = 0; c < 2; c++) hprev[s][ri][c] = 0.0f;
        #pragma unroll
        for (int rg = 0; rg < 4; rg++) {
            acc[s][0][rg] = 0.0f;
            acc[s][1][rg] = 0.0f;
            acc[s][2][rg] = bias_n[rg & 1];
        }
    }

    #pragma unroll 1
    for (int t = 0; t < TT; t++) {
        const int tcol = dir ? (TT - 1 - t) : t;
        const int* tokrow = g_tokT + tcol * BATCH + b0r;

        // xp gather for both streams (coalesced tokens, L2-resident table)
        float2 xp[2][2][3];
        #pragma unroll
        for (int s = 0; s < 2; s++)
            #pragma unroll
            for (int ri = 0; ri < 2; ri++) {
                int tok = tokrow[16 * s + 8 * ri + lr];
                const float2* xr = (const float2*)(xt + tok * GG + 24 * w);
                #pragma unroll
                for (int u = 0; u < 3; u++)
                    xp[s][ri][u] = xr[4 * u + lq];
            }

        #pragma unroll
        for (int ph = 0; ph < 2; ph++) {
            const int sm_ = 1 - ph;   // mma stream
            const int sg  = ph;       // gate stream

            // reset mma-stream accumulators
            #pragma unroll
            for (int rg = 0; rg < 4; rg++) {
                acc[sm_][0][rg] = 0.0f;
                acc[sm_][1][rg] = 0.0f;
                acc[sm_][2][rg] = bias_n[rg & 1];
            }

            const bool do_mma = ph ? (t < TT - 1) : (t > 0);
            const uint32_t ab0 = sb + SH16(sm_) + ar * 256;

            #pragma unroll
            for (int kc2 = 0; kc2 < 4; kc2++) {
                uint32_t a0[8];
                if (do_mma) {
                    uint32_t clo = (uint32_t)(((4 * kc2 + ahi) ^ asw) << 4);
                    uint32_t chi = (uint32_t)(((4 * kc2 + 2 + ahi) ^ asw) << 4);
                    ldsm4(a0[0], a0[1], a0[2], a0[3], ab0 + clo);
                    ldsm4(a0[4], a0[5], a0[6], a0[7], ab0 + chi);
                }

                // one gate cell of the gate stream, interleaved with mma
                {
                    const int ri = kc2 >> 1, c01 = kc2 & 1, rg = 2 * ri + c01;
                    float xr_ = (c01 ? xp[sg][ri][0].y : xp[sg][ri][0].x)
                                + acc[sg][0][rg];
                    float xz_ = (c01 ? xp[sg][ri][1].y : xp[sg][ri][1].x)
                                + acc[sg][1][rg];
                    float xn_ = (c01 ? xp[sg][ri][2].y : xp[sg][ri][2].x);
                    float nh  = acc[sg][2][rg];
                    float r = sigm_fast(xr_);
                    float z = sigm_fast(xz_);
                    float n = tanh_precise(fmaf(r, nh, xn_));
                    float h = fmaf(z, hprev[sg][ri][c01] - n, n);
                    hprev[sg][ri][c01] = h;
                    *(__half*)(smem + SH16(sg) + stoff[ri] + 2 * c01) =
                        __float2half_rn(h);
                }

                if (do_mma) {
                    mma16816(acc[sm_][0], a0 + 0, Brg[0][kc2][0], Brg[0][kc2][1]);
                    mma16816(acc[sm_][0], a0 + 4, Brg[0][kc2][2], Brg[0][kc2][3]);
                    mma16816(acc[sm_][1], a0 + 0, Brg[1][kc2][0], Brg[1][kc2][1]);
                    mma16816(acc[sm_][1], a0 + 4, Brg[1][kc2][2], Brg[1][kc2][3]);
                    uint32_t bh[4];
                    const uint32_t chunk =
                        (uint32_t)(((4 * kc2 + bj) ^ bsw) << 4);
                    ldsm4(bh[0], bh[1], bh[2], bh[3],
                          sb + SW0 + brow + 2 * 2048 + chunk);
                    mma16816(acc[sm_][2], a0 + 0, bh[0], bh[1]);
                    mma16816(acc[sm_][2], a0 + 4, bh[2], bh[3]);
                }
            }
            __syncthreads();
        }
    }

    // final hidden -> feat
    #pragma unroll
    for (int s = 0; s < 2; s++)
        #pragma unroll
        for (int ri = 0; ri < 2; ri++)
            #pragma unroll
            for (int c = 0; c < 2; c++) {
                int m = 16 * s + lr + 8 * ri;
                int j = 8 * w + 2 * lq + c;
                g_feat[(b0r + m) * EE + dir * HH + j] = hprev[s][ri][c];
            }
}

// ---------------------------------------------------------------------------
// Head: one row per warp; down-proj via 8-lane groups; then thread-per-column
// projection over the CTA's 8 rows. grid 256 x 256 threads.
// ---------------------------------------------------------------------------
#define HB 8
__global__ __launch_bounds__(256) void head_kernel(
    const int* __restrict__ lang_ids,
    const float* __restrict__ down_w, const float* __restrict__ down_b,
    const float* __restrict__ up_b,
    const float* __restrict__ ln_g,   const float* __restrict__ ln_b,
    const float* __restrict__ proj_w, const float* __restrict__ proj_b,
    float* __restrict__ out) {
    __shared__ float y_s[HB][EE];
    const int tid = threadIdx.x, w = tid >> 5, lane = tid & 31;
    const int b0 = blockIdx.x * HB;
    const int b = b0 + w;
    const int l = lang_ids[b];
    const float* fb = g_feat + b * EE;

    float4 f4[8];
    #pragma unroll
    for (int c = 0; c < 8; c++)
        f4[c] = *(const float4*)(fb + (lane & 7) * 4 + 32 * c);

    float hid = 0.0f;
    const float* dwb = down_w + l * BNK * EE;
    #pragma unroll
    for (int g = 0; g < 8; g++) {
        const int d = 4 * g + (lane >> 3);
        const float* wr = dwb + d * EE + (lane & 7) * 4;
        float s = 0.0f;
        #pragma unroll
        for (int c = 0; c < 8; c++) {
            float4 wv = *(const float4*)(wr + 32 * c);
            s = fmaf(f4[c].x, wv.x, s); s = fmaf(f4[c].y, wv.y, s);
            s = fmaf(f4[c].z, wv.z, s); s = fmaf(f4[c].w, wv.w, s);
        }
        s += __shfl_xor_sync(0xffffffffu, s, 1);
        s += __shfl_xor_sync(0xffffffffu, s, 2);
        s += __shfl_xor_sync(0xffffffffu, s, 4);
        float got = __shfl_sync(0xffffffffu, s, (lane & 3) * 8);
        if ((lane >> 2) == g) hid = got;
    }
    hid += down_b[l * BNK + lane];
    hid = 0.5f * hid * (1.0f + erff(hid * 0.7071067811865476f));

    const float4 fx0 = *(const float4*)(fb + lane * 8);
    const float4 fx1 = *(const float4*)(fb + lane * 8 + 4);
    float4 a0 = *(const float4*)(up_b + l * EE + lane * 8);
    float4 a1 = *(const float4*)(up_b + l * EE + lane * 8 + 4);
    const float* uwb = g_upwT + l * BNK * EE;
    #pragma unroll 4
    for (int d = 0; d < BNK; d++) {
        float hd = __shfl_sync(0xffffffffu, hid, d);
        float4 u0 = *(const float4*)(uwb + d * EE + lane * 8);
        float4 u1 = *(const float4*)(uwb + d * EE + lane * 8 + 4);
        a0.x = fmaf(hd, u0.x, a0.x); a0.y = fmaf(hd, u0.y, a0.y);
        a0.z = fmaf(hd, u0.z, a0.z); a0.w = fmaf(hd, u0.w, a0.w);
        a1.x = fmaf(hd, u1.x, a1.x); a1.y = fmaf(hd, u1.y, a1.y);
        a1.z = fmaf(hd, u1.z, a1.z); a1.w = fmaf(hd, u1.w, a1.w);
    }
    float x[8] = {fx0.x + a0.x, fx0.y + a0.y, fx0.z + a0.z, fx0.w + a0.w,
                  fx1.x + a1.x, fx1.y + a1.y, fx1.z + a1.z, fx1.w + a1.w};
    float s1 = 0.0f, s2 = 0.0f;
    #pragma unroll
    for (int j = 0; j < 8; j++) { s1 += x[j]; s2 = fmaf(x[j], x[j], s2); }
    #pragma unroll
    for (int o = 16; o; o >>= 1) {
        s1 += __shfl_xor_sync(0xffffffffu, s1, o);
        s2 += __shfl_xor_sync(0xffffffffu, s2, o);
    }
    const float mu = s1 * (1.0f / EE);
    const float rstd = rsqrtf(s2 * (1.0f / EE) - mu * mu + 1e-5f);
    const float4 g0 = *(const float4*)(ln_g + l * EE + lane * 8);
    const float4 g1 = *(const float4*)(ln_g + l * EE + lane * 8 + 4);
    const float4 bb0 = *(const float4*)(ln_b + l * EE + lane * 8);
    const float4 bb1 = *(const float4*)(ln_b + l * EE + lane * 8 + 4);
    float4 y0, y1;
    y0.x = (x[0]-mu)*rstd*g0.x + bb0.x;  y0.y = (x[1]-mu)*rstd*g0.y + bb0.y;
    y0.z = (x[2]-mu)*rstd*g0.z + bb0.z;  y0.w = (x[3]-mu)*rstd*g0.w + bb0.w;
    y1.x = (x[4]-mu)*rstd*g1.x + bb1.x;  y1.y = (x[5]-mu)*rstd*g1.y + bb1.y;
    y1.z = (x[6]-mu)*rstd*g1.z + bb1.z;  y1.w = (x[7]-mu)*rstd*g1.w + bb1.w;
    *(float4*)(&y_s[w][lane * 8])     = y0;
    *(float4*)(&y_s[w][lane * 8 + 4]) = y1;
    __syncthreads();

    float accv[HB];
    #pragma unroll
    for (int r = 0; r < HB; r++) accv[r] = proj_b[tid];
    const float* pw = proj_w + tid * EE;
    for (int e = 0; e < EE; e += 4) {
        float4 wv = *(const float4*)(pw + e);
        #pragma unroll
        for (int r = 0; r < HB; r++) {
            float4 yv = *(const float4*)(&y_s[r][e]);
            accv[r] = fmaf(wv.x, yv.x, accv[r]);
            accv[r] = fmaf(wv.y, yv.y, accv[r]);
            accv[r] = fmaf(wv.z, yv.z, accv[r]);
            accv[r] = fmaf(wv.w, yv.w, accv[r]);
        }
    }
    #pragma unroll
    for (int r = 0; r < HB; r++) out[(b0 + r) * OO + tid] = accv[r];
}

// ---------------------------------------------------------------------------
extern "C" void kernel_launch(void* const* d_in, const int* in_sizes, int n_in,
                              void* d_out, int out_size) {
    const int*   tokens = (const int*)d_in[0];
    const int*   lang   = (const int*)d_in[1];
    const float* ce     = (const float*)d_in[2];
    const float* wih_f  = (const float*)d_in[3];
    const float* whh_f  = (const float*)d_in[4];
    const float* bih_f  = (const float*)d_in[5];
    const float* bhh_f  = (const float*)d_in[6];
    const float* wih_b  = (const float*)d_in[7];
    const float* whh_b  = (const float*)d_in[8];
    const float* bih_b  = (const float*)d_in[9];
    const float* bhh_b  = (const float*)d_in[10];
    const float* down_w = (const float*)d_in[11];
    const float* down_b = (const float*)d_in[12];
    const float* up_w   = (const float*)d_in[13];
    const float* up_b   = (const float*)d_in[14];
    const float* ln_g   = (const float*)d_in[15];
    const float* ln_b   = (const float*)d_in[16];
    const float* proj_w = (const float*)d_in[17];
    const float* proj_b = (const float*)d_in[18];
    float* out = (float*)d_out;

    cudaFuncSetAttribute(gru_mma_kernel,
                         cudaFuncAttributeMaxDynamicSharedMemorySize, SMEM_TOTAL);
    const size_t xsmem = (size_t)(GG * CC + GG + 32 * CC) * sizeof(float);
    cudaFuncSetAttribute(xtab_kernel,
                         cudaFuncAttributeMaxDynamicSharedMemorySize, (int)xsmem);

    wsplit_kernel<<<dim3(2, GG), HH>>>(whh_f, whh_b);
    xtab_kernel<<<dim3(8, 2), GG, xsmem>>>(ce, wih_f, bih_f, wih_b, bih_b,
                                           bhh_f, bhh_b);
    upwT_kernel<<<96, 256>>>(up_w);
    tokT_kernel<<<(BATCH * TT + 255) / 256, 256>>>(tokens);
    gru_mma_kernel<<<dim3(BATCH / BM, 2), NTH, SMEM_TOTAL>>>(bhh_f, bhh_b);
    head_kernel<<<BATCH / HB, 256>>>(lang, down_w, down_b, up_b,
                                     ln_g, ln_b, proj_w, proj_b, out);
}